// round 11
// baseline (speedup 1.0000x reference)
#include <cuda_runtime.h>
#include <cuda_fp16.h>
#include <cstdint>

#define B_SZ  2
#define HEADS 16
#define TKN   2048
#define DM    1024
#define DK    64

// ---- fp16 mma / ldmatrix / f16x2 helpers ----
__device__ __forceinline__ uint32_t cvta_s(const void* p) {
    return (uint32_t)__cvta_generic_to_shared(p);
}
__device__ __forceinline__ void ldm4(uint32_t* r, uint32_t a) {
    asm volatile("ldmatrix.sync.aligned.m8n8.x4.shared.b16 {%0,%1,%2,%3},[%4];"
        : "=r"(r[0]), "=r"(r[1]), "=r"(r[2]), "=r"(r[3]) : "r"(a));
}
__device__ __forceinline__ void ldm4t(uint32_t* r, uint32_t a) {
    asm volatile("ldmatrix.sync.aligned.m8n8.x4.trans.shared.b16 {%0,%1,%2,%3},[%4];"
        : "=r"(r[0]), "=r"(r[1]), "=r"(r[2]), "=r"(r[3]) : "r"(a));
}
__device__ __forceinline__ void mmah(float* d, uint32_t a0, uint32_t a1, uint32_t a2,
                                     uint32_t a3, uint32_t b0, uint32_t b1) {
    asm("mma.sync.aligned.m16n8k16.row.col.f32.f16.f16.f32 "
        "{%0,%1,%2,%3},{%4,%5,%6,%7},{%8,%9},{%0,%1,%2,%3};"
        : "+f"(d[0]), "+f"(d[1]), "+f"(d[2]), "+f"(d[3])
        : "r"(a0), "r"(a1), "r"(a2), "r"(a3), "r"(b0), "r"(b1));
}
__device__ __forceinline__ uint32_t cvt2h(float hi, float lo) {
    uint32_t d; asm("cvt.rn.f16x2.f32 %0, %1, %2;" : "=r"(d) : "f"(hi), "f"(lo)); return d;
}
__device__ __forceinline__ uint32_t ex2h2(uint32_t x) {
    uint32_t d; asm("ex2.approx.f16x2 %0, %1;" : "=r"(d) : "r"(x)); return d;
}
__device__ __forceinline__ float ex2f(float x) {
    float d; asm("ex2.approx.ftz.f32 %0, %1;" : "=f"(d) : "f"(x)); return d;
}
__device__ __forceinline__ uint32_t hadd2u(uint32_t a, uint32_t b) {
    uint32_t d; asm("add.rn.f16x2 %0, %1, %2;" : "=r"(d) : "r"(a), "r"(b)); return d;
}
__device__ __forceinline__ float h2sumf(uint32_t h) {
    __half2 v = *(__half2*)&h;
    return __low2float(v) + __high2float(v);
}
// cp.async 16B
__device__ __forceinline__ void cp16(uint32_t d, const void* s) {
    asm volatile("cp.async.ca.shared.global [%0], [%1], 16;" :: "r"(d), "l"(s));
}
__device__ __forceinline__ void cpcommit() { asm volatile("cp.async.commit_group;"); }
template <int N>
__device__ __forceinline__ void cpwait() {
    asm volatile("cp.async.wait_group %0;" :: "n"(N));
}

// ---- device-global scratch (no allocation) ----
__device__ __half g_Xf[3][B_SZ * TKN * DM];      // f16(X) for Q,K,V inputs
__device__ __half g_Wf[3][HEADS * DM * DK];      // f16(W) for Wq,Wk,Wv  [h][k][n]
__device__ __half g_Wof[DM * DM];                // f16(Wo)              [j][k]
__device__ __half g_Qh[B_SZ * HEADS * TKN * DK]; // pre-scaled by 1/8
__device__ __half g_Kh[B_SZ * HEADS * TKN * DK];
__device__ __half g_Vh[B_SZ * HEADS * TKN * DK];
__device__ __half g_ctxh[B_SZ * HEADS * TKN * DK];

// ---------------------------------------------------------------------------
// Kernel 0: fused f32 -> f16 convert for all 7 tensors (blockIdx.y selects).
// ---------------------------------------------------------------------------
__global__ __launch_bounds__(256) void split_kernel(
    const float* __restrict__ Q, const float* __restrict__ K, const float* __restrict__ V,
    const float* __restrict__ Wq, const float* __restrict__ Wk, const float* __restrict__ Wv,
    const float* __restrict__ Wo)
{
    int y = blockIdx.y;
    const float* src; __half* dst; int n4;
    switch (y) {
        case 0: src = Q;  dst = g_Xf[0]; n4 = (B_SZ * TKN * DM) / 4; break;
        case 1: src = K;  dst = g_Xf[1]; n4 = (B_SZ * TKN * DM) / 4; break;
        case 2: src = V;  dst = g_Xf[2]; n4 = (B_SZ * TKN * DM) / 4; break;
        case 3: src = Wq; dst = g_Wf[0]; n4 = (HEADS * DM * DK) / 4; break;
        case 4: src = Wk; dst = g_Wf[1]; n4 = (HEADS * DM * DK) / 4; break;
        case 5: src = Wv; dst = g_Wf[2]; n4 = (HEADS * DM * DK) / 4; break;
        default: src = Wo; dst = g_Wof;  n4 = (DM * DM) / 4; break;
    }
    int i = blockIdx.x * blockDim.x + threadIdx.x;
    int stride = gridDim.x * blockDim.x;
    for (; i < n4; i += stride) {
        float4 v = ((const float4*)src)[i];
        ((__half2*)dst)[2 * i]     = __floats2half2_rn(v.x, v.y);
        ((__half2*)dst)[2 * i + 1] = __floats2half2_rn(v.z, v.w);
    }
}

// ---------------------------------------------------------------------------
// Kernel 1: QKV projections. CTA tile 128(t) x 64(one head), 512 thr, 16 warps.
// Warp grid 4(M) x 4(N); warp tile 32x16 -> 16 acc regs/thread.
// 4-stage cp.async ring, distance 2 -> one sync/iter.
// smem per stage: X[128][40] (10240B) + W[32][72] (4608B) = 14848 B.
// ---------------------------------------------------------------------------
#define P2_W_OFF   10240
#define P2_STAGE_B 14848

__global__ __launch_bounds__(512, 2) void proj_kernel(
    const float* __restrict__ bq, const float* __restrict__ bk, const float* __restrict__ bv)
{
    extern __shared__ __half sdyn[];
    __shared__ float sBias[64];

    int z = blockIdx.z;
    const float* bias = (z == 0) ? bq : (z == 1) ? bk : bv;
    __half* out = (z == 0) ? g_Qh : (z == 1) ? g_Kh : g_Vh;
    float oscale = (z == 0) ? 0.125f : 1.0f;

    int y = blockIdx.y;                 // 0..31: b*16 + h
    int b = y >> 4, h = y & 15;
    int t0 = blockIdx.x * 128;

    const __half* Xp = g_Xf[z] + ((size_t)b * TKN + t0) * DM;
    const __half* Wp = g_Wf[z] + (size_t)h * DM * DK;    // [k][n=64]

    int tid = threadIdx.x;
    int lane = tid & 31, w = tid >> 5;
    int wm = w & 3, wn = w >> 2;        // 4(M) x 4(N)
    int g = lane >> 2, tg = lane & 3;

    if (tid < 64) sBias[tid] = bias[h * DK + tid];

    uint32_t sb0 = cvta_s(sdyn);

    // staging coords: X 512 cp16 (1/thread); W 256 cp16 (tid<256)
    int xr = tid >> 2, xs = tid & 3;
    int wr = tid >> 3, wc = (tid & 7) * 8;

    float acc[2][2][4];
#pragma unroll
    for (int mt = 0; mt < 2; mt++)
#pragma unroll
        for (int nt = 0; nt < 2; nt++)
#pragma unroll
            for (int q = 0; q < 4; q++) acc[mt][nt][q] = 0.0f;

    int arow = wm * 32 + ((lane >> 3) & 1) * 8 + (lane & 7);
    int acol = (lane >> 4) * 8;
    uint32_t a_off = (uint32_t)(arow * 40 + acol) * 2;
    uint32_t w_off = ((uint32_t)((lane >> 3) * 8 + (lane & 7)) * 72) * 2;

    auto stage = [&](int s, int d0) {
        uint32_t base = sb0 + s * P2_STAGE_B;
        cp16(base + (uint32_t)(xr * 40 + xs * 8) * 2,
             Xp + (size_t)xr * DM + d0 + xs * 8);
        if (tid < 256)
            cp16(base + P2_W_OFF + (uint32_t)(wr * 72 + wc) * 2,
                 Wp + (size_t)(d0 + wr) * DK + wc);
        cpcommit();
    };

    stage(0, 0); stage(1, 32);

    const int nIter = DM / 32;
    for (int it = 0; it < nIter; it++) {
        if (it + 2 < nIter) { stage((it + 2) & 3, (it + 2) * 32); cpwait<2>(); }
        else if (it + 1 < nIter) cpwait<1>();
        else cpwait<0>();
        __syncthreads();

        uint32_t base = sb0 + (it & 3) * P2_STAGE_B;
        uint32_t abh = base + a_off;
        uint32_t wbh = base + P2_W_OFF + w_off;

        uint32_t AH[2][2][4];
#pragma unroll
        for (int mt = 0; mt < 2; mt++)
#pragma unroll
            for (int ks = 0; ks < 2; ks++)
                ldm4(AH[mt][ks], abh + (mt * 16 * 40 + ks * 16) * 2);

        uint32_t BH[2][4];
#pragma unroll
        for (int nt = 0; nt < 2; nt++)
            ldm4t(BH[nt], wbh + (wn * 16 + nt * 8) * 2);

#pragma unroll
        for (int ks = 0; ks < 2; ks++)
#pragma unroll
            for (int nt = 0; nt < 2; nt++)
#pragma unroll
                for (int mt = 0; mt < 2; mt++)
                    mmah(acc[mt][nt],
                         AH[mt][ks][0], AH[mt][ks][1], AH[mt][ks][2], AH[mt][ks][3],
                         BH[nt][2 * ks], BH[nt][2 * ks + 1]);
    }

    __half* outh = out + ((size_t)(b * HEADS + h) * TKN + t0) * DK;
#pragma unroll
    for (int mt = 0; mt < 2; mt++) {
        int r0 = wm * 32 + mt * 16 + g;
#pragma unroll
        for (int nt = 0; nt < 2; nt++) {
            int cl = wn * 16 + nt * 8 + 2 * tg;
            float b0v = sBias[cl], b1v = sBias[cl + 1];
            *(__half2*)(outh + (size_t)r0 * DK + cl) =
                __floats2half2_rn((acc[mt][nt][0] + b0v) * oscale, (acc[mt][nt][1] + b1v) * oscale);
            *(__half2*)(outh + (size_t)(r0 + 8) * DK + cl) =
                __floats2half2_rn((acc[mt][nt][2] + b0v) * oscale, (acc[mt][nt][3] + b1v) * oscale);
        }
    }
}

// ---------------------------------------------------------------------------
// Kernel 2: flash attention (R8 version): 128 queries / 8 warps per CTA,
// K/V double-buffered via cp.async.
// ---------------------------------------------------------------------------
__global__ __launch_bounds__(256) void flash_kernel()
{
    __shared__ __half Qs[128][72];
    __shared__ __half Ks[2][64][72];
    __shared__ __half Vs[2][64][72];

    const float C = 1.4426950408889634f;
    const uint32_t BUFB = 64 * 72 * 2;

    int bh = blockIdx.y;
    int t0 = blockIdx.x * 128;
    const __half* Qp = g_Qh + (size_t)bh * TKN * DK;
    const __half* Kp = g_Kh + (size_t)bh * TKN * DK;
    const __half* Vp = g_Vh + (size_t)bh * TKN * DK;

    int tid = threadIdx.x;
    int lane = tid & 31, w = tid >> 5;
    int wq = w >> 2, wi = w & 3;
    int g = lane >> 2, tg = lane & 3;

    uint32_t ksb = cvta_s(Ks), vsb = cvta_s(Vs);

    auto stagekv = [&](int buf, int s0) {
#pragma unroll
        for (int i = 0; i < 2; i++) {
            int idx = i * 256 + tid;
            int r = idx >> 3, c = idx & 7;
            uint32_t dof = (uint32_t)(r * 72 + c * 8) * 2;
            cp16(ksb + buf * BUFB + dof, Kp + (size_t)(s0 + r) * DK + c * 8);
            cp16(vsb + buf * BUFB + dof, Vp + (size_t)(s0 + r) * DK + c * 8);
        }
        cpcommit();
    };

    stagekv(0, 0);

#pragma unroll
    for (int i = 0; i < 4; i++) {
        int idx = i * 256 + tid;
        int r = idx >> 3, c = idx & 7;
        *(uint4*)&Qs[r][c * 8] = *(const uint4*)(Qp + (size_t)(t0 + r) * DK + c * 8);
    }
    __syncthreads();

    uint32_t Qa[4][4];
    {
        int qrow = wq * 64 + wi * 16 + ((lane >> 3) & 1) * 8 + (lane & 7);
        int qcol = (lane >> 4) * 8;
        uint32_t qbase = cvta_s(&Qs[qrow][qcol]);
#pragma unroll
        for (int ks = 0; ks < 4; ks++) ldm4(Qa[ks], qbase + ks * 32);
    }

    uint32_t k_off = (((lane & 7) * 72 + (lane >> 3) * 8) << 1);
    uint32_t v_off = ((((lane >> 3) * 8 + (lane & 7)) * 72) << 1);

    float m0 = -1e30f, m1 = -1e30f, l0 = 0.0f, l1 = 0.0f;
    float O[8][4];
#pragma unroll
    for (int nt = 0; nt < 8; nt++)
#pragma unroll
        for (int q = 0; q < 4; q++) O[nt][q] = 0.0f;

    const int nCh = TKN / 64;
    for (int it = 0; it < nCh; it++) {
        if (it > 0) __syncthreads();
        if (it + 1 < nCh) { stagekv((it + 1) & 1, (it + 1) * 64); cpwait<1>(); }
        else              { cpwait<0>(); }
        __syncthreads();

        uint32_t kbase = ksb + (it & 1) * BUFB + k_off;
        uint32_t vbase = vsb + (it & 1) * BUFB + v_off;

        float S[8][4];
#pragma unroll
        for (int nt = 0; nt < 8; nt++) {
#pragma unroll
            for (int q = 0; q < 4; q++) S[nt][q] = 0.0f;
            uint32_t bk[8];
            uint32_t ka = kbase + ((nt * 8 * 72) << 1);
            ldm4(bk,     ka);
            ldm4(bk + 4, ka + 64);
#pragma unroll
            for (int ks = 0; ks < 4; ks++)
                mmah(S[nt], Qa[ks][0], Qa[ks][1], Qa[ks][2], Qa[ks][3],
                     bk[2 * ks], bk[2 * ks + 1]);
        }

        float mx0 = fmaxf(S[0][0], S[0][1]);
        float mx1 = fmaxf(S[0][2], S[0][3]);
#pragma unroll
        for (int nt = 1; nt < 8; nt++) {
            mx0 = fmaxf(mx0, fmaxf(S[nt][0], S[nt][1]));
            mx1 = fmaxf(mx1, fmaxf(S[nt][2], S[nt][3]));
        }
        mx0 = fmaxf(mx0, __shfl_xor_sync(0xffffffffu, mx0, 1));
        mx0 = fmaxf(mx0, __shfl_xor_sync(0xffffffffu, mx0, 2));
        mx1 = fmaxf(mx1, __shfl_xor_sync(0xffffffffu, mx1, 1));
        mx1 = fmaxf(mx1, __shfl_xor_sync(0xffffffffu, mx1, 2));

        float mn0 = fmaxf(m0, mx0), mn1 = fmaxf(m1, mx1);
        float corr0 = ex2f((m0 - mn0) * C);
        float corr1 = ex2f((m1 - mn1) * C);
        m0 = mn0; m1 = mn1;
        float mc0 = mn0 * C, mc1 = mn1 * C;

        uint32_t P01[8], P23[8];
#pragma unroll
        for (int nt = 0; nt < 8; nt++) {
            P01[nt] = ex2h2(cvt2h(fmaf(S[nt][1], C, -mc0), fmaf(S[nt][0], C, -mc0)));
            P23[nt] = ex2h2(cvt2h(fmaf(S[nt][3], C, -mc1), fmaf(S[nt][2], C, -mc1)));
        }

        uint32_t s01 = hadd2u(hadd2u(hadd2u(P01[0], P01[1]), hadd2u(P01[2], P01[3])),
                              hadd2u(hadd2u(P01[4], P01[5]), hadd2u(P01[6], P01[7])));
        uint32_t s23 = hadd2u(hadd2u(hadd2u(P23[0], P23[1]), hadd2u(P23[2], P23[3])),
                              hadd2u(hadd2u(P23[4], P23[5]), hadd2u(P23[6], P23[7])));
        float rs0 = h2sumf(s01), rs1 = h2sumf(s23);
        rs0 += __shfl_xor_sync(0xffffffffu, rs0, 1);
        rs0 += __shfl_xor_sync(0xffffffffu, rs0, 2);
        rs1 += __shfl_xor_sync(0xffffffffu, rs1, 1);
        rs1 += __shfl_xor_sync(0xffffffffu, rs1, 2);
        l0 = l0 * corr0 + rs0;
        l1 = l1 * corr1 + rs1;

#pragma unroll
        for (int nt = 0; nt < 8; nt++) {
            O[nt][0] *= corr0; O[nt][1] *= corr0;
            O[nt][2] *= corr1; O[nt][3] *= corr1;
        }

#pragma unroll
        for (int nt = 0; nt < 8; nt++) {
            uint32_t bv[8];
            uint32_t va = vbase + ((nt * 8) << 1);
            ldm4t(bv,     va);
            ldm4t(bv + 4, va + ((32 * 72) << 1));
#pragma unroll
            for (int ks = 0; ks < 4; ks++)
                mmah(O[nt], P01[2 * ks], P23[2 * ks], P01[2 * ks + 1], P23[2 * ks + 1],
                     bv[2 * ks], bv[2 * ks + 1]);
        }
    }

    float inv0 = 1.0f / l0, inv1 = 1.0f / l1;
    size_t cb = (size_t)bh * TKN * DK;
    int r0 = t0 + wq * 64 + wi * 16 + g;
#pragma unroll
    for (int nt = 0; nt < 8; nt++) {
        int col = nt * 8 + 2 * tg;
        *(__half2*)(g_ctxh + cb + (size_t)r0 * DK + col) =
            __floats2half2_rn(O[nt][0] * inv0, O[nt][1] * inv0);
        *(__half2*)(g_ctxh + cb + (size_t)(r0 + 8) * DK + col) =
            __floats2half2_rn(O[nt][2] * inv1, O[nt][3] * inv1);
    }
}

// ---------------------------------------------------------------------------
// Kernel 3: output projection. CTA tile 128(m) x 64(j), 512 thr, 16 warps,
// warp tile 32x16. 4-stage ring, distance 2 -> one sync/iter.
// smem per stage: A[128][40] (10240B) + B[64][40] (5120B) = 15360 B.
// ---------------------------------------------------------------------------
#define O2_B_OFF   10240
#define O2_STAGE_B 15360

__global__ __launch_bounds__(512, 2) void outproj_kernel(
    const float* __restrict__ bo, float* __restrict__ out)
{
    extern __shared__ __half sdyn2[];
    __shared__ float sBias[64];

    int j0 = blockIdx.x * 64;
    int m0 = blockIdx.y * 128;

    int tid = threadIdx.x;
    int lane = tid & 31, w = tid >> 5;
    int wm = w & 3, wn = w >> 2;
    int g = lane >> 2, tg = lane & 3;

    if (tid < 64) sBias[tid] = bo[j0 + tid];

    uint32_t sb0 = cvta_s(sdyn2);
    int xr = tid >> 2, xs = tid & 3;          // A loader: 1 cp16/thread
    int br = tid >> 2, bs = tid & 3;          // B loader (tid<256): 64 rows x 4 segs

    float acc[2][2][4];
#pragma unroll
    for (int mt = 0; mt < 2; mt++)
#pragma unroll
        for (int nt = 0; nt < 2; nt++)
#pragma unroll
            for (int q = 0; q < 4; q++) acc[mt][nt][q] = 0.0f;

    int arow = wm * 32 + ((lane >> 3) & 1) * 8 + (lane & 7);
    int acol = (lane >> 4) * 8;
    uint32_t a_off = (uint32_t)(arow * 40 + acol) * 2;
    uint32_t k_off = (uint32_t)((lane & 7) * 40 + (lane >> 3) * 8) * 2;

    auto stage = [&](int s, int d0) {
        uint32_t base = sb0 + s * O2_STAGE_B;
        cp16(base + (uint32_t)(xr * 40 + xs * 8) * 2,
             g_ctxh + (size_t)(m0 + xr) * DM + d0 + xs * 8);
        if (tid < 256)
            cp16(base + O2_B_OFF + (uint32_t)(br * 40 + bs * 8) * 2,
                 g_Wof + (size_t)(j0 + br) * DM + d0 + bs * 8);
        cpcommit();
    };

    stage(0, 0); stage(1, 32);

    const int nIter = DM / 32;
    for (int it = 0; it < nIter; it++) {
        if (it + 2 < nIter) { stage((it + 2) & 3, (it + 2) * 32); cpwait<2>(); }
        else if (it + 1 < nIter) cpwait<1>();
        else cpwait<0>();
        __syncthreads();

        uint32_t base = sb0 + (it & 3) * O2_STAGE_B;
        uint32_t abh = base + a_off;
        uint32_t kbh = base + O2_B_OFF + k_off;

        uint32_t AH[2][2][4];
#pragma unroll
        for (int mt = 0; mt < 2; mt++)
#pragma unroll
            for (int ks = 0; ks < 2; ks++)
                ldm4(AH[mt][ks], abh + (mt * 16 * 40 + ks * 16) * 2);

        uint32_t BH[2][4];
#pragma unroll
        for (int nt = 0; nt < 2; nt++)
            ldm4(BH[nt], kbh + ((wn * 16 + nt * 8) * 40) * 2);

#pragma unroll
        for (int ks = 0; ks < 2; ks++)
#pragma unroll
            for (int nt = 0; nt < 2; nt++)
#pragma unroll
                for (int mt = 0; mt < 2; mt++)
                    mmah(acc[mt][nt],
                         AH[mt][ks][0], AH[mt][ks][1], AH[mt][ks][2], AH[mt][ks][3],
                         BH[nt][2 * ks], BH[nt][2 * ks + 1]);
    }

#pragma unroll
    for (int mt = 0; mt < 2; mt++) {
        int r0 = m0 + wm * 32 + mt * 16 + g;
#pragma unroll
        for (int nt = 0; nt < 2; nt++) {
            int cl = wn * 16 + nt * 8 + 2 * tg;
            float b0v = sBias[cl], b1v = sBias[cl + 1];
            *(float2*)(out + (size_t)r0 * DM + j0 + cl) =
                make_float2(acc[mt][nt][0] + b0v, acc[mt][nt][1] + b1v);
            *(float2*)(out + (size_t)(r0 + 8) * DM + j0 + cl) =
                make_float2(acc[mt][nt][2] + b0v, acc[mt][nt][3] + b1v);
        }
    }
}

// ---------------------------------------------------------------------------
extern "C" void kernel_launch(void* const* d_in, const int* in_sizes, int n_in,
                              void* d_out, int out_size)
{
    const float* Q  = (const float*)d_in[0];
    const float* K  = (const float*)d_in[1];
    const float* V  = (const float*)d_in[2];
    const float* Wq = (const float*)d_in[3];
    const float* bq = (const float*)d_in[4];
    const float* Wk = (const float*)d_in[5];
    const float* bk = (const float*)d_in[6];
    const float* Wv = (const float*)d_in[7];
    const float* bv = (const float*)d_in[8];
    const float* Wo = (const float*)d_in[9];
    const float* bo = (const float*)d_in[10];
    float* out = (float*)d_out;

    cudaFuncSetAttribute(proj_kernel, cudaFuncAttributeMaxDynamicSharedMemorySize, 4 * P2_STAGE_B);
    cudaFuncSetAttribute(outproj_kernel, cudaFuncAttributeMaxDynamicSharedMemorySize, 4 * O2_STAGE_B);

    dim3 gs(128, 7);
    split_kernel<<<gs, 256>>>(Q, K, V, Wq, Wk, Wv, Wo);

    dim3 g1(TKN / 128, B_SZ * HEADS, 3);
    proj_kernel<<<g1, 512, 4 * P2_STAGE_B>>>(bq, bk, bv);

    dim3 g2(TKN / 128, B_SZ * HEADS);
    flash_kernel<<<g2, 256>>>();

    dim3 g3(DM / 64, (B_SZ * TKN) / 128);
    outproj_kernel<<<g3, 512, 4 * O2_STAGE_B>>>(bo, out);
}

// round 12
// speedup vs baseline: 1.1977x; 1.1977x over previous
#include <cuda_runtime.h>
#include <cuda_fp16.h>
#include <cstdint>

#define B_SZ  2
#define HEADS 16
#define TKN   2048
#define DM    1024
#define DK    64

// ---- fp16 mma / ldmatrix / f16x2 helpers ----
__device__ __forceinline__ uint32_t cvta_s(const void* p) {
    return (uint32_t)__cvta_generic_to_shared(p);
}
__device__ __forceinline__ void ldm4(uint32_t* r, uint32_t a) {
    asm volatile("ldmatrix.sync.aligned.m8n8.x4.shared.b16 {%0,%1,%2,%3},[%4];"
        : "=r"(r[0]), "=r"(r[1]), "=r"(r[2]), "=r"(r[3]) : "r"(a));
}
__device__ __forceinline__ void ldm4t(uint32_t* r, uint32_t a) {
    asm volatile("ldmatrix.sync.aligned.m8n8.x4.trans.shared.b16 {%0,%1,%2,%3},[%4];"
        : "=r"(r[0]), "=r"(r[1]), "=r"(r[2]), "=r"(r[3]) : "r"(a));
}
__device__ __forceinline__ void mmah(float* d, uint32_t a0, uint32_t a1, uint32_t a2,
                                     uint32_t a3, uint32_t b0, uint32_t b1) {
    asm("mma.sync.aligned.m16n8k16.row.col.f32.f16.f16.f32 "
        "{%0,%1,%2,%3},{%4,%5,%6,%7},{%8,%9},{%0,%1,%2,%3};"
        : "+f"(d[0]), "+f"(d[1]), "+f"(d[2]), "+f"(d[3])
        : "r"(a0), "r"(a1), "r"(a2), "r"(a3), "r"(b0), "r"(b1));
}
__device__ __forceinline__ uint32_t cvt2h(float hi, float lo) {
    uint32_t d; asm("cvt.rn.f16x2.f32 %0, %1, %2;" : "=r"(d) : "f"(hi), "f"(lo)); return d;
}
__device__ __forceinline__ uint32_t ex2h2(uint32_t x) {
    uint32_t d; asm("ex2.approx.f16x2 %0, %1;" : "=r"(d) : "r"(x)); return d;
}
__device__ __forceinline__ float ex2f(float x) {
    float d; asm("ex2.approx.ftz.f32 %0, %1;" : "=f"(d) : "f"(x)); return d;
}
__device__ __forceinline__ uint32_t hadd2u(uint32_t a, uint32_t b) {
    uint32_t d; asm("add.rn.f16x2 %0, %1, %2;" : "=r"(d) : "r"(a), "r"(b)); return d;
}
__device__ __forceinline__ float h2sumf(uint32_t h) {
    __half2 v = *(__half2*)&h;
    return __low2float(v) + __high2float(v);
}
// cp.async 16B
__device__ __forceinline__ void cp16(uint32_t d, const void* s) {
    asm volatile("cp.async.ca.shared.global [%0], [%1], 16;" :: "r"(d), "l"(s));
}
__device__ __forceinline__ void cpcommit() { asm volatile("cp.async.commit_group;"); }
template <int N>
__device__ __forceinline__ void cpwait() {
    asm volatile("cp.async.wait_group %0;" :: "n"(N));
}

// ---- device-global scratch (no allocation) ----
__device__ __half g_Xf[3][B_SZ * TKN * DM];      // f16(X) for Q,K,V inputs
__device__ __half g_Wf[3][HEADS * DM * DK];      // f16(W) for Wq,Wk,Wv
__device__ __half g_Wof[DM * DM];                // f16(Wo)
__device__ __half g_Qh[B_SZ * HEADS * TKN * DK]; // pre-scaled by 1/8
__device__ __half g_Kh[B_SZ * HEADS * TKN * DK];
__device__ __half g_Vh[B_SZ * HEADS * TKN * DK];
__device__ __half g_ctxh[B_SZ * HEADS * TKN * DK];

// ---------------------------------------------------------------------------
// Kernel 0: fused f32 -> f16 convert for all 7 tensors (blockIdx.y selects).
// ---------------------------------------------------------------------------
__global__ __launch_bounds__(256) void split_kernel(
    const float* __restrict__ Q, const float* __restrict__ K, const float* __restrict__ V,
    const float* __restrict__ Wq, const float* __restrict__ Wk, const float* __restrict__ Wv,
    const float* __restrict__ Wo)
{
    int y = blockIdx.y;
    const float* src; __half* dst; int n4;
    switch (y) {
        case 0: src = Q;  dst = g_Xf[0]; n4 = (B_SZ * TKN * DM) / 4; break;
        case 1: src = K;  dst = g_Xf[1]; n4 = (B_SZ * TKN * DM) / 4; break;
        case 2: src = V;  dst = g_Xf[2]; n4 = (B_SZ * TKN * DM) / 4; break;
        case 3: src = Wq; dst = g_Wf[0]; n4 = (HEADS * DM * DK) / 4; break;
        case 4: src = Wk; dst = g_Wf[1]; n4 = (HEADS * DM * DK) / 4; break;
        case 5: src = Wv; dst = g_Wf[2]; n4 = (HEADS * DM * DK) / 4; break;
        default: src = Wo; dst = g_Wof;  n4 = (DM * DM) / 4; break;
    }
    int i = blockIdx.x * blockDim.x + threadIdx.x;
    int stride = gridDim.x * blockDim.x;
    for (; i < n4; i += stride) {
        float4 v = ((const float4*)src)[i];
        ((__half2*)dst)[2 * i]     = __floats2half2_rn(v.x, v.y);
        ((__half2*)dst)[2 * i + 1] = __floats2half2_rn(v.z, v.w);
    }
}

// ---------------------------------------------------------------------------
// Kernel 1: QKV projections. CTA 128(t) x 128(2 heads), 256 thr, 8 warps
// (4M x 2N), warp tile 32x64. 4-stage ring, distance 2 -> one sync/iter.
// smem per stage (halfs): X[128][40] @0 (5120), W[32][136] @5120 (4352).
// ---------------------------------------------------------------------------
#define P_W   5120
#define P_STAGE_B 18944

__global__ __launch_bounds__(256, 2) void proj_kernel(
    const float* __restrict__ bq, const float* __restrict__ bk, const float* __restrict__ bv)
{
    extern __shared__ __half sdyn[];
    __shared__ float sBias[128];

    int z = blockIdx.z;
    const float* bias = (z == 0) ? bq : (z == 1) ? bk : bv;
    __half* out = (z == 0) ? g_Qh : (z == 1) ? g_Kh : g_Vh;
    float oscale = (z == 0) ? 0.125f : 1.0f;

    int y = blockIdx.y;
    int b = y >> 3, h0 = (y & 7) * 2;
    int t0 = blockIdx.x * 128;

    const __half* Xp = g_Xf[z] + ((size_t)b * TKN + t0) * DM;
    const __half* Wp = g_Wf[z] + (size_t)h0 * DM * DK;

    int tid = threadIdx.x;
    int lane = tid & 31, w = tid >> 5;
    int wm = w & 3, wn = w >> 2;
    int g = lane >> 2, tg = lane & 3;

    if (tid < 128) sBias[tid] = bias[h0 * DK + tid];

    uint32_t sb0 = cvta_s(sdyn);

    int xrow = tid >> 2, xseg = tid & 3;
    int wrow_c = tid >> 4, wcol_c = (tid & 15) * 8;
    size_t wso = (size_t)(wcol_c >= 64 ? DM * DK : 0) + (size_t)wrow_c * DK + (wcol_c & 63);

    float acc[2][8][4];
#pragma unroll
    for (int mt = 0; mt < 2; mt++)
#pragma unroll
        for (int nt = 0; nt < 8; nt++)
#pragma unroll
            for (int q = 0; q < 4; q++) acc[mt][nt][q] = 0.0f;

    int arow = wm * 32 + ((lane >> 3) & 1) * 8 + (lane & 7);
    int acol = (lane >> 4) * 8;
    uint32_t a_off = (uint32_t)(arow * 40 + acol) * 2;
    uint32_t w_off = ((uint32_t)((lane >> 3) * 8 + (lane & 7)) * 136) * 2;

    auto stage = [&](int s, int d0) {
        uint32_t base = sb0 + s * P_STAGE_B;
#pragma unroll
        for (int i = 0; i < 2; i++) {
            int r = xrow + i * 64;
            cp16(base + (uint32_t)(r * 40 + xseg * 8) * 2,
                 Xp + (size_t)r * DM + d0 + xseg * 8);
        }
#pragma unroll
        for (int i = 0; i < 2; i++) {
            int r = wrow_c + i * 16;
            cp16(base + P_W * 2 + (uint32_t)(r * 136 + wcol_c) * 2,
                 Wp + wso + (size_t)(d0 + i * 16) * DK);
        }
        cpcommit();
    };

    stage(0, 0); stage(1, 32);

    const int nIter = DM / 32;
    for (int it = 0; it < nIter; it++) {
        if (it + 2 < nIter) { stage((it + 2) & 3, (it + 2) * 32); cpwait<2>(); }
        else if (it + 1 < nIter) cpwait<1>();
        else cpwait<0>();
        __syncthreads();

        uint32_t base = sb0 + (it & 3) * P_STAGE_B;
        uint32_t abh = base + a_off;
        uint32_t wbh = base + P_W * 2 + w_off;

        uint32_t AH[2][2][4];
#pragma unroll
        for (int mt = 0; mt < 2; mt++)
#pragma unroll
            for (int ks = 0; ks < 2; ks++)
                ldm4(AH[mt][ks], abh + (mt * 16 * 40 + ks * 16) * 2);

#pragma unroll
        for (int grp = 0; grp < 2; grp++) {
            uint32_t BH[4][4];
#pragma unroll
            for (int n4i = 0; n4i < 4; n4i++)
                ldm4t(BH[n4i], wbh + (wn * 64 + (grp * 4 + n4i) * 8) * 2);
#pragma unroll
            for (int ks = 0; ks < 2; ks++)
#pragma unroll
                for (int n4i = 0; n4i < 4; n4i++)
#pragma unroll
                    for (int mt = 0; mt < 2; mt++)
                        mmah(acc[mt][grp * 4 + n4i],
                             AH[mt][ks][0], AH[mt][ks][1], AH[mt][ks][2], AH[mt][ks][3],
                             BH[n4i][2 * ks], BH[n4i][2 * ks + 1]);
        }
    }

    __half* outh = out + ((size_t)(b * HEADS + h0 + wn) * TKN + t0) * DK;
#pragma unroll
    for (int mt = 0; mt < 2; mt++) {
        int r0 = wm * 32 + mt * 16 + g;
#pragma unroll
        for (int nt = 0; nt < 8; nt++) {
            int cl = nt * 8 + 2 * tg;
            float b0v = sBias[wn * 64 + cl], b1v = sBias[wn * 64 + cl + 1];
            *(__half2*)(outh + (size_t)r0 * DK + cl) =
                __floats2half2_rn((acc[mt][nt][0] + b0v) * oscale, (acc[mt][nt][1] + b1v) * oscale);
            *(__half2*)(outh + (size_t)(r0 + 8) * DK + cl) =
                __floats2half2_rn((acc[mt][nt][2] + b0v) * oscale, (acc[mt][nt][3] + b1v) * oscale);
        }
    }
}

// ---------------------------------------------------------------------------
// Kernel 2: flash attention (R8 version): 128 queries / 8 warps per CTA,
// K/V double-buffered via cp.async (2 syncs/chunk — measured fastest).
// ---------------------------------------------------------------------------
__global__ __launch_bounds__(256) void flash_kernel()
{
    __shared__ __half Qs[128][72];
    __shared__ __half Ks[2][64][72];
    __shared__ __half Vs[2][64][72];

    const float C = 1.4426950408889634f;
    const uint32_t BUFB = 64 * 72 * 2;

    int bh = blockIdx.y;
    int t0 = blockIdx.x * 128;
    const __half* Qp = g_Qh + (size_t)bh * TKN * DK;
    const __half* Kp = g_Kh + (size_t)bh * TKN * DK;
    const __half* Vp = g_Vh + (size_t)bh * TKN * DK;

    int tid = threadIdx.x;
    int lane = tid & 31, w = tid >> 5;
    int wq = w >> 2, wi = w & 3;
    int g = lane >> 2, tg = lane & 3;

    uint32_t ksb = cvta_s(Ks), vsb = cvta_s(Vs);

    auto stagekv = [&](int buf, int s0) {
#pragma unroll
        for (int i = 0; i < 2; i++) {
            int idx = i * 256 + tid;
            int r = idx >> 3, c = idx & 7;
            uint32_t dof = (uint32_t)(r * 72 + c * 8) * 2;
            cp16(ksb + buf * BUFB + dof, Kp + (size_t)(s0 + r) * DK + c * 8);
            cp16(vsb + buf * BUFB + dof, Vp + (size_t)(s0 + r) * DK + c * 8);
        }
        cpcommit();
    };

    stagekv(0, 0);

#pragma unroll
    for (int i = 0; i < 4; i++) {
        int idx = i * 256 + tid;
        int r = idx >> 3, c = idx & 7;
        *(uint4*)&Qs[r][c * 8] = *(const uint4*)(Qp + (size_t)(t0 + r) * DK + c * 8);
    }
    __syncthreads();

    uint32_t Qa[4][4];
    {
        int qrow = wq * 64 + wi * 16 + ((lane >> 3) & 1) * 8 + (lane & 7);
        int qcol = (lane >> 4) * 8;
        uint32_t qbase = cvta_s(&Qs[qrow][qcol]);
#pragma unroll
        for (int ks = 0; ks < 4; ks++) ldm4(Qa[ks], qbase + ks * 32);
    }

    uint32_t k_off = (((lane & 7) * 72 + (lane >> 3) * 8) << 1);
    uint32_t v_off = ((((lane >> 3) * 8 + (lane & 7)) * 72) << 1);

    float m0 = -1e30f, m1 = -1e30f, l0 = 0.0f, l1 = 0.0f;
    float O[8][4];
#pragma unroll
    for (int nt = 0; nt < 8; nt++)
#pragma unroll
        for (int q = 0; q < 4; q++) O[nt][q] = 0.0f;

    const int nCh = TKN / 64;
    for (int it = 0; it < nCh; it++) {
        if (it > 0) __syncthreads();
        if (it + 1 < nCh) { stagekv((it + 1) & 1, (it + 1) * 64); cpwait<1>(); }
        else              { cpwait<0>(); }
        __syncthreads();

        uint32_t kbase = ksb + (it & 1) * BUFB + k_off;
        uint32_t vbase = vsb + (it & 1) * BUFB + v_off;

        float S[8][4];
#pragma unroll
        for (int nt = 0; nt < 8; nt++) {
#pragma unroll
            for (int q = 0; q < 4; q++) S[nt][q] = 0.0f;
            uint32_t bk[8];
            uint32_t ka = kbase + ((nt * 8 * 72) << 1);
            ldm4(bk,     ka);
            ldm4(bk + 4, ka + 64);
#pragma unroll
            for (int ks = 0; ks < 4; ks++)
                mmah(S[nt], Qa[ks][0], Qa[ks][1], Qa[ks][2], Qa[ks][3],
                     bk[2 * ks], bk[2 * ks + 1]);
        }

        float mx0 = fmaxf(S[0][0], S[0][1]);
        float mx1 = fmaxf(S[0][2], S[0][3]);
#pragma unroll
        for (int nt = 1; nt < 8; nt++) {
            mx0 = fmaxf(mx0, fmaxf(S[nt][0], S[nt][1]));
            mx1 = fmaxf(mx1, fmaxf(S[nt][2], S[nt][3]));
        }
        mx0 = fmaxf(mx0, __shfl_xor_sync(0xffffffffu, mx0, 1));
        mx0 = fmaxf(mx0, __shfl_xor_sync(0xffffffffu, mx0, 2));
        mx1 = fmaxf(mx1, __shfl_xor_sync(0xffffffffu, mx1, 1));
        mx1 = fmaxf(mx1, __shfl_xor_sync(0xffffffffu, mx1, 2));

        float mn0 = fmaxf(m0, mx0), mn1 = fmaxf(m1, mx1);
        float corr0 = ex2f((m0 - mn0) * C);
        float corr1 = ex2f((m1 - mn1) * C);
        m0 = mn0; m1 = mn1;
        float mc0 = mn0 * C, mc1 = mn1 * C;

        uint32_t P01[8], P23[8];
#pragma unroll
        for (int nt = 0; nt < 8; nt++) {
            P01[nt] = ex2h2(cvt2h(fmaf(S[nt][1], C, -mc0), fmaf(S[nt][0], C, -mc0)));
            P23[nt] = ex2h2(cvt2h(fmaf(S[nt][3], C, -mc1), fmaf(S[nt][2], C, -mc1)));
        }

        uint32_t s01 = hadd2u(hadd2u(hadd2u(P01[0], P01[1]), hadd2u(P01[2], P01[3])),
                              hadd2u(hadd2u(P01[4], P01[5]), hadd2u(P01[6], P01[7])));
        uint32_t s23 = hadd2u(hadd2u(hadd2u(P23[0], P23[1]), hadd2u(P23[2], P23[3])),
                              hadd2u(hadd2u(P23[4], P23[5]), hadd2u(P23[6], P23[7])));
        float rs0 = h2sumf(s01), rs1 = h2sumf(s23);
        rs0 += __shfl_xor_sync(0xffffffffu, rs0, 1);
        rs0 += __shfl_xor_sync(0xffffffffu, rs0, 2);
        rs1 += __shfl_xor_sync(0xffffffffu, rs1, 1);
        rs1 += __shfl_xor_sync(0xffffffffu, rs1, 2);
        l0 = l0 * corr0 + rs0;
        l1 = l1 * corr1 + rs1;

#pragma unroll
        for (int nt = 0; nt < 8; nt++) {
            O[nt][0] *= corr0; O[nt][1] *= corr0;
            O[nt][2] *= corr1; O[nt][3] *= corr1;
        }

#pragma unroll
        for (int nt = 0; nt < 8; nt++) {
            uint32_t bv[8];
            uint32_t va = vbase + ((nt * 8) << 1);
            ldm4t(bv,     va);
            ldm4t(bv + 4, va + ((32 * 72) << 1));
#pragma unroll
            for (int ks = 0; ks < 4; ks++)
                mmah(O[nt], P01[2 * ks], P23[2 * ks], P01[2 * ks + 1], P23[2 * ks + 1],
                     bv[2 * ks], bv[2 * ks + 1]);
        }
    }

    float inv0 = 1.0f / l0, inv1 = 1.0f / l1;
    size_t cb = (size_t)bh * TKN * DK;
    int r0 = t0 + wq * 64 + wi * 16 + g;
#pragma unroll
    for (int nt = 0; nt < 8; nt++) {
        int col = nt * 8 + 2 * tg;
        *(__half2*)(g_ctxh + cb + (size_t)r0 * DK + col) =
            __floats2half2_rn(O[nt][0] * inv0, O[nt][1] * inv0);
        *(__half2*)(g_ctxh + cb + (size_t)(r0 + 8) * DK + col) =
            __floats2half2_rn(O[nt][2] * inv1, O[nt][3] * inv1);
    }
}

// ---------------------------------------------------------------------------
// Kernel 3: output projection (R9 version: 128x128, 4-stage ring, distance 2).
// ---------------------------------------------------------------------------
#define O_BH 5120
#define O_STAGE_B 20480

__global__ __launch_bounds__(256, 2) void outproj_kernel(
    const float* __restrict__ bo, float* __restrict__ out)
{
    extern __shared__ __half sdyn2[];
    __shared__ float sBias[128];

    int j0 = blockIdx.x * 128;
    int m0 = blockIdx.y * 128;

    int tid = threadIdx.x;
    int lane = tid & 31, w = tid >> 5;
    int wm = w & 3, wn = w >> 2;
    int g = lane >> 2, tg = lane & 3;

    if (tid < 128) sBias[tid] = bo[j0 + tid];

    uint32_t sb0 = cvta_s(sdyn2);
    int xrow = tid >> 2, xseg = tid & 3;

    float acc[2][8][4];
#pragma unroll
    for (int mt = 0; mt < 2; mt++)
#pragma unroll
        for (int nt = 0; nt < 8; nt++)
#pragma unroll
            for (int q = 0; q < 4; q++) acc[mt][nt][q] = 0.0f;

    int arow = wm * 32 + ((lane >> 3) & 1) * 8 + (lane & 7);
    int acol = (lane >> 4) * 8;
    uint32_t a_off = (uint32_t)(arow * 40 + acol) * 2;
    uint32_t k_off = (uint32_t)((lane & 7) * 40 + (lane >> 3) * 8) * 2;

    auto stage = [&](int s, int d0) {
        uint32_t base = sb0 + s * O_STAGE_B;
#pragma unroll
        for (int i = 0; i < 2; i++) {
            int r = xrow + i * 64;
            uint32_t dof = (uint32_t)(r * 40 + xseg * 8) * 2;
            cp16(base + dof,            g_ctxh + (size_t)(m0 + r) * DM + d0 + xseg * 8);
            cp16(base + O_BH * 2 + dof, g_Wof  + (size_t)(j0 + r) * DM + d0 + xseg * 8);
        }
        cpcommit();
    };

    stage(0, 0); stage(1, 32);

    const int nIter = DM / 32;
    for (int it = 0; it < nIter; it++) {
        if (it + 2 < nIter) { stage((it + 2) & 3, (it + 2) * 32); cpwait<2>(); }
        else if (it + 1 < nIter) cpwait<1>();
        else cpwait<0>();
        __syncthreads();

        uint32_t base = sb0 + (it & 3) * O_STAGE_B;
        uint32_t abh = base + a_off;
        uint32_t kbh = base + O_BH * 2 + k_off;

        uint32_t AH[2][2][4];
#pragma unroll
        for (int mt = 0; mt < 2; mt++)
#pragma unroll
            for (int ks = 0; ks < 2; ks++)
                ldm4(AH[mt][ks], abh + (mt * 16 * 40 + ks * 16) * 2);

#pragma unroll
        for (int grp = 0; grp < 2; grp++) {
            uint32_t BH[4][4];
#pragma unroll
            for (int n4i = 0; n4i < 4; n4i++)
                ldm4(BH[n4i], kbh + ((wn * 64 + (grp * 4 + n4i) * 8) * 40) * 2);
#pragma unroll
            for (int ks = 0; ks < 2; ks++)
#pragma unroll
                for (int n4i = 0; n4i < 4; n4i++)
#pragma unroll
                    for (int mt = 0; mt < 2; mt++)
                        mmah(acc[mt][grp * 4 + n4i],
                             AH[mt][ks][0], AH[mt][ks][1], AH[mt][ks][2], AH[mt][ks][3],
                             BH[n4i][2 * ks], BH[n4i][2 * ks + 1]);
        }
    }

#pragma unroll
    for (int mt = 0; mt < 2; mt++) {
        int r0 = m0 + wm * 32 + mt * 16 + g;
#pragma unroll
        for (int nt = 0; nt < 8; nt++) {
            int cl = wn * 64 + nt * 8 + 2 * tg;
            float b0v = sBias[cl], b1v = sBias[cl + 1];
            *(float2*)(out + (size_t)r0 * DM + j0 + cl) =
                make_float2(acc[mt][nt][0] + b0v, acc[mt][nt][1] + b1v);
            *(float2*)(out + (size_t)(r0 + 8) * DM + j0 + cl) =
                make_float2(acc[mt][nt][2] + b0v, acc[mt][nt][3] + b1v);
        }
    }
}

// ---------------------------------------------------------------------------
extern "C" void kernel_launch(void* const* d_in, const int* in_sizes, int n_in,
                              void* d_out, int out_size)
{
    const float* Q  = (const float*)d_in[0];
    const float* K  = (const float*)d_in[1];
    const float* V  = (const float*)d_in[2];
    const float* Wq = (const float*)d_in[3];
    const float* bq = (const float*)d_in[4];
    const float* Wk = (const float*)d_in[5];
    const float* bk = (const float*)d_in[6];
    const float* Wv = (const float*)d_in[7];
    const float* bv = (const float*)d_in[8];
    const float* Wo = (const float*)d_in[9];
    const float* bo = (const float*)d_in[10];
    float* out = (float*)d_out;

    cudaFuncSetAttribute(proj_kernel, cudaFuncAttributeMaxDynamicSharedMemorySize, 4 * P_STAGE_B);
    cudaFuncSetAttribute(outproj_kernel, cudaFuncAttributeMaxDynamicSharedMemorySize, 4 * O_STAGE_B);

    dim3 gs(128, 7);
    split_kernel<<<gs, 256>>>(Q, K, V, Wq, Wk, Wv, Wo);

    dim3 g1(TKN / 128, B_SZ * 8, 3);
    proj_kernel<<<g1, 256, 4 * P_STAGE_B>>>(bq, bk, bv);

    dim3 g2(TKN / 128, B_SZ * HEADS);
    flash_kernel<<<g2, 256>>>();

    dim3 g3(DM / 128, (B_SZ * TKN) / 128);
    outproj_kernel<<<g3, 256, 4 * O_STAGE_B>>>(bo, out);
}

// round 13
// speedup vs baseline: 1.2175x; 1.0166x over previous
#include <cuda_runtime.h>
#include <cuda_fp16.h>
#include <cstdint>

#define B_SZ  2
#define HEADS 16
#define TKN   2048
#define DM    1024
#define DK    64

// ---- fp16 mma / ldmatrix / f16x2 helpers ----
__device__ __forceinline__ uint32_t cvta_s(const void* p) {
    return (uint32_t)__cvta_generic_to_shared(p);
}
__device__ __forceinline__ void ldm4(uint32_t* r, uint32_t a) {
    asm volatile("ldmatrix.sync.aligned.m8n8.x4.shared.b16 {%0,%1,%2,%3},[%4];"
        : "=r"(r[0]), "=r"(r[1]), "=r"(r[2]), "=r"(r[3]) : "r"(a));
}
__device__ __forceinline__ void ldm4t(uint32_t* r, uint32_t a) {
    asm volatile("ldmatrix.sync.aligned.m8n8.x4.trans.shared.b16 {%0,%1,%2,%3},[%4];"
        : "=r"(r[0]), "=r"(r[1]), "=r"(r[2]), "=r"(r[3]) : "r"(a));
}
__device__ __forceinline__ void mmah(float* d, uint32_t a0, uint32_t a1, uint32_t a2,
                                     uint32_t a3, uint32_t b0, uint32_t b1) {
    asm("mma.sync.aligned.m16n8k16.row.col.f32.f16.f16.f32 "
        "{%0,%1,%2,%3},{%4,%5,%6,%7},{%8,%9},{%0,%1,%2,%3};"
        : "+f"(d[0]), "+f"(d[1]), "+f"(d[2]), "+f"(d[3])
        : "r"(a0), "r"(a1), "r"(a2), "r"(a3), "r"(b0), "r"(b1));
}
__device__ __forceinline__ uint32_t cvt2h(float hi, float lo) {
    uint32_t d; asm("cvt.rn.f16x2.f32 %0, %1, %2;" : "=r"(d) : "f"(hi), "f"(lo)); return d;
}
__device__ __forceinline__ uint32_t ex2h2(uint32_t x) {
    uint32_t d; asm("ex2.approx.f16x2 %0, %1;" : "=r"(d) : "r"(x)); return d;
}
__device__ __forceinline__ float ex2f(float x) {
    float d; asm("ex2.approx.ftz.f32 %0, %1;" : "=f"(d) : "f"(x)); return d;
}
__device__ __forceinline__ uint32_t hadd2u(uint32_t a, uint32_t b) {
    uint32_t d; asm("add.rn.f16x2 %0, %1, %2;" : "=r"(d) : "r"(a), "r"(b)); return d;
}
__device__ __forceinline__ float h2sumf(uint32_t h) {
    __half2 v = *(__half2*)&h;
    return __low2float(v) + __high2float(v);
}
// cp.async 16B
__device__ __forceinline__ void cp16(uint32_t d, const void* s) {
    asm volatile("cp.async.ca.shared.global [%0], [%1], 16;" :: "r"(d), "l"(s));
}
__device__ __forceinline__ void cpcommit() { asm volatile("cp.async.commit_group;"); }
template <int N>
__device__ __forceinline__ void cpwait() {
    asm volatile("cp.async.wait_group %0;" :: "n"(N));
}

// ---- device-global scratch (no allocation) ----
__device__ __half g_Xf[3][B_SZ * TKN * DM];      // f16(X) for Q,K,V inputs
__device__ __half g_Wf[3][HEADS * DM * DK];      // f16(W) for Wq,Wk,Wv
__device__ __half g_Wof[DM * DM];                // f16(Wo)
__device__ __half g_Qh[B_SZ * HEADS * TKN * DK]; // pre-scaled by 1/8
__device__ __half g_Kh[B_SZ * HEADS * TKN * DK];
__device__ __half g_Vh[B_SZ * HEADS * TKN * DK];
__device__ __half g_ctxh[B_SZ * HEADS * TKN * DK];

// ---------------------------------------------------------------------------
// Kernel 0: fused f32 -> f16 convert for all 7 tensors (blockIdx.y selects).
// ---------------------------------------------------------------------------
__global__ __launch_bounds__(256) void split_kernel(
    const float* __restrict__ Q, const float* __restrict__ K, const float* __restrict__ V,
    const float* __restrict__ Wq, const float* __restrict__ Wk, const float* __restrict__ Wv,
    const float* __restrict__ Wo)
{
    int y = blockIdx.y;
    const float* src; __half* dst; int n4;
    switch (y) {
        case 0: src = Q;  dst = g_Xf[0]; n4 = (B_SZ * TKN * DM) / 4; break;
        case 1: src = K;  dst = g_Xf[1]; n4 = (B_SZ * TKN * DM) / 4; break;
        case 2: src = V;  dst = g_Xf[2]; n4 = (B_SZ * TKN * DM) / 4; break;
        case 3: src = Wq; dst = g_Wf[0]; n4 = (HEADS * DM * DK) / 4; break;
        case 4: src = Wk; dst = g_Wf[1]; n4 = (HEADS * DM * DK) / 4; break;
        case 5: src = Wv; dst = g_Wf[2]; n4 = (HEADS * DM * DK) / 4; break;
        default: src = Wo; dst = g_Wof;  n4 = (DM * DM) / 4; break;
    }
    int i = blockIdx.x * blockDim.x + threadIdx.x;
    int stride = gridDim.x * blockDim.x;
    for (; i < n4; i += stride) {
        float4 v = ((const float4*)src)[i];
        ((__half2*)dst)[2 * i]     = __floats2half2_rn(v.x, v.y);
        ((__half2*)dst)[2 * i + 1] = __floats2half2_rn(v.z, v.w);
    }
}

// ---------------------------------------------------------------------------
// Kernel 1: QKV projections. CTA 128(t) x 128(2 heads), 256 thr, 8 warps
// (4M x 2N), warp tile 32x64. 4-stage ring, distance 2 -> one sync/iter.
// All 12 fragment loads hoisted to iteration top (single exposed LDSM latency).
// smem per stage (halfs): X[128][40] @0 (5120), W[32][136] @5120 (4352).
// ---------------------------------------------------------------------------
#define P_W   5120
#define P_STAGE_B 18944

__global__ __launch_bounds__(256, 2) void proj_kernel(
    const float* __restrict__ bq, const float* __restrict__ bk, const float* __restrict__ bv)
{
    extern __shared__ __half sdyn[];
    __shared__ float sBias[128];

    int z = blockIdx.z;
    const float* bias = (z == 0) ? bq : (z == 1) ? bk : bv;
    __half* out = (z == 0) ? g_Qh : (z == 1) ? g_Kh : g_Vh;
    float oscale = (z == 0) ? 0.125f : 1.0f;

    int y = blockIdx.y;
    int b = y >> 3, h0 = (y & 7) * 2;
    int t0 = blockIdx.x * 128;

    const __half* Xp = g_Xf[z] + ((size_t)b * TKN + t0) * DM;
    const __half* Wp = g_Wf[z] + (size_t)h0 * DM * DK;

    int tid = threadIdx.x;
    int lane = tid & 31, w = tid >> 5;
    int wm = w & 3, wn = w >> 2;
    int g = lane >> 2, tg = lane & 3;

    if (tid < 128) sBias[tid] = bias[h0 * DK + tid];

    uint32_t sb0 = cvta_s(sdyn);

    int xrow = tid >> 2, xseg = tid & 3;
    int wrow_c = tid >> 4, wcol_c = (tid & 15) * 8;
    size_t wso = (size_t)(wcol_c >= 64 ? DM * DK : 0) + (size_t)wrow_c * DK + (wcol_c & 63);

    float acc[2][8][4];
#pragma unroll
    for (int mt = 0; mt < 2; mt++)
#pragma unroll
        for (int nt = 0; nt < 8; nt++)
#pragma unroll
            for (int q = 0; q < 4; q++) acc[mt][nt][q] = 0.0f;

    int arow = wm * 32 + ((lane >> 3) & 1) * 8 + (lane & 7);
    int acol = (lane >> 4) * 8;
    uint32_t a_off = (uint32_t)(arow * 40 + acol) * 2;
    uint32_t w_off = ((uint32_t)((lane >> 3) * 8 + (lane & 7)) * 136) * 2;

    auto stage = [&](int s, int d0) {
        uint32_t base = sb0 + s * P_STAGE_B;
#pragma unroll
        for (int i = 0; i < 2; i++) {
            int r = xrow + i * 64;
            cp16(base + (uint32_t)(r * 40 + xseg * 8) * 2,
                 Xp + (size_t)r * DM + d0 + xseg * 8);
        }
#pragma unroll
        for (int i = 0; i < 2; i++) {
            int r = wrow_c + i * 16;
            cp16(base + P_W * 2 + (uint32_t)(r * 136 + wcol_c) * 2,
                 Wp + wso + (size_t)(d0 + i * 16) * DK);
        }
        cpcommit();
    };

    stage(0, 0); stage(1, 32);

    const int nIter = DM / 32;
    for (int it = 0; it < nIter; it++) {
        if (it + 2 < nIter) { stage((it + 2) & 3, (it + 2) * 32); cpwait<2>(); }
        else if (it + 1 < nIter) cpwait<1>();
        else cpwait<0>();
        __syncthreads();

        uint32_t base = sb0 + (it & 3) * P_STAGE_B;
        uint32_t abh = base + a_off;
        uint32_t wbh = base + P_W * 2 + w_off;

        // hoist ALL fragment loads: 4 A + 8 B ldmatrix up-front
        uint32_t AH[2][2][4];
#pragma unroll
        for (int mt = 0; mt < 2; mt++)
#pragma unroll
            for (int ks = 0; ks < 2; ks++)
                ldm4(AH[mt][ks], abh + (mt * 16 * 40 + ks * 16) * 2);

        uint32_t BH[8][4];
#pragma unroll
        for (int nt = 0; nt < 8; nt++)
            ldm4t(BH[nt], wbh + (wn * 64 + nt * 8) * 2);

#pragma unroll
        for (int nt = 0; nt < 8; nt++)
#pragma unroll
            for (int ks = 0; ks < 2; ks++)
#pragma unroll
                for (int mt = 0; mt < 2; mt++)
                    mmah(acc[mt][nt],
                         AH[mt][ks][0], AH[mt][ks][1], AH[mt][ks][2], AH[mt][ks][3],
                         BH[nt][2 * ks], BH[nt][2 * ks + 1]);
    }

    __half* outh = out + ((size_t)(b * HEADS + h0 + wn) * TKN + t0) * DK;
#pragma unroll
    for (int mt = 0; mt < 2; mt++) {
        int r0 = wm * 32 + mt * 16 + g;
#pragma unroll
        for (int nt = 0; nt < 8; nt++) {
            int cl = nt * 8 + 2 * tg;
            float b0v = sBias[wn * 64 + cl], b1v = sBias[wn * 64 + cl + 1];
            *(__half2*)(outh + (size_t)r0 * DK + cl) =
                __floats2half2_rn((acc[mt][nt][0] + b0v) * oscale, (acc[mt][nt][1] + b1v) * oscale);
            *(__half2*)(outh + (size_t)(r0 + 8) * DK + cl) =
                __floats2half2_rn((acc[mt][nt][2] + b0v) * oscale, (acc[mt][nt][3] + b1v) * oscale);
        }
    }
}

// ---------------------------------------------------------------------------
// Kernel 2: flash attention (R8/R12 version, measured fastest): 128 queries /
// 8 warps per CTA, K/V double-buffered via cp.async.
// ---------------------------------------------------------------------------
__global__ __launch_bounds__(256) void flash_kernel()
{
    __shared__ __half Qs[128][72];
    __shared__ __half Ks[2][64][72];
    __shared__ __half Vs[2][64][72];

    const float C = 1.4426950408889634f;
    const uint32_t BUFB = 64 * 72 * 2;

    int bh = blockIdx.y;
    int t0 = blockIdx.x * 128;
    const __half* Qp = g_Qh + (size_t)bh * TKN * DK;
    const __half* Kp = g_Kh + (size_t)bh * TKN * DK;
    const __half* Vp = g_Vh + (size_t)bh * TKN * DK;

    int tid = threadIdx.x;
    int lane = tid & 31, w = tid >> 5;
    int wq = w >> 2, wi = w & 3;
    int g = lane >> 2, tg = lane & 3;

    uint32_t ksb = cvta_s(Ks), vsb = cvta_s(Vs);

    auto stagekv = [&](int buf, int s0) {
#pragma unroll
        for (int i = 0; i < 2; i++) {
            int idx = i * 256 + tid;
            int r = idx >> 3, c = idx & 7;
            uint32_t dof = (uint32_t)(r * 72 + c * 8) * 2;
            cp16(ksb + buf * BUFB + dof, Kp + (size_t)(s0 + r) * DK + c * 8);
            cp16(vsb + buf * BUFB + dof, Vp + (size_t)(s0 + r) * DK + c * 8);
        }
        cpcommit();
    };

    stagekv(0, 0);

#pragma unroll
    for (int i = 0; i < 4; i++) {
        int idx = i * 256 + tid;
        int r = idx >> 3, c = idx & 7;
        *(uint4*)&Qs[r][c * 8] = *(const uint4*)(Qp + (size_t)(t0 + r) * DK + c * 8);
    }
    __syncthreads();

    uint32_t Qa[4][4];
    {
        int qrow = wq * 64 + wi * 16 + ((lane >> 3) & 1) * 8 + (lane & 7);
        int qcol = (lane >> 4) * 8;
        uint32_t qbase = cvta_s(&Qs[qrow][qcol]);
#pragma unroll
        for (int ks = 0; ks < 4; ks++) ldm4(Qa[ks], qbase + ks * 32);
    }

    uint32_t k_off = (((lane & 7) * 72 + (lane >> 3) * 8) << 1);
    uint32_t v_off = ((((lane >> 3) * 8 + (lane & 7)) * 72) << 1);

    float m0 = -1e30f, m1 = -1e30f, l0 = 0.0f, l1 = 0.0f;
    float O[8][4];
#pragma unroll
    for (int nt = 0; nt < 8; nt++)
#pragma unroll
        for (int q = 0; q < 4; q++) O[nt][q] = 0.0f;

    const int nCh = TKN / 64;
    for (int it = 0; it < nCh; it++) {
        if (it > 0) __syncthreads();
        if (it + 1 < nCh) { stagekv((it + 1) & 1, (it + 1) * 64); cpwait<1>(); }
        else              { cpwait<0>(); }
        __syncthreads();

        uint32_t kbase = ksb + (it & 1) * BUFB + k_off;
        uint32_t vbase = vsb + (it & 1) * BUFB + v_off;

        float S[8][4];
#pragma unroll
        for (int nt = 0; nt < 8; nt++) {
#pragma unroll
            for (int q = 0; q < 4; q++) S[nt][q] = 0.0f;
            uint32_t bk[8];
            uint32_t ka = kbase + ((nt * 8 * 72) << 1);
            ldm4(bk,     ka);
            ldm4(bk + 4, ka + 64);
#pragma unroll
            for (int ks = 0; ks < 4; ks++)
                mmah(S[nt], Qa[ks][0], Qa[ks][1], Qa[ks][2], Qa[ks][3],
                     bk[2 * ks], bk[2 * ks + 1]);
        }

        float mx0 = fmaxf(S[0][0], S[0][1]);
        float mx1 = fmaxf(S[0][2], S[0][3]);
#pragma unroll
        for (int nt = 1; nt < 8; nt++) {
            mx0 = fmaxf(mx0, fmaxf(S[nt][0], S[nt][1]));
            mx1 = fmaxf(mx1, fmaxf(S[nt][2], S[nt][3]));
        }
        mx0 = fmaxf(mx0, __shfl_xor_sync(0xffffffffu, mx0, 1));
        mx0 = fmaxf(mx0, __shfl_xor_sync(0xffffffffu, mx0, 2));
        mx1 = fmaxf(mx1, __shfl_xor_sync(0xffffffffu, mx1, 1));
        mx1 = fmaxf(mx1, __shfl_xor_sync(0xffffffffu, mx1, 2));

        float mn0 = fmaxf(m0, mx0), mn1 = fmaxf(m1, mx1);
        float corr0 = ex2f((m0 - mn0) * C);
        float corr1 = ex2f((m1 - mn1) * C);
        m0 = mn0; m1 = mn1;
        float mc0 = mn0 * C, mc1 = mn1 * C;

        uint32_t P01[8], P23[8];
#pragma unroll
        for (int nt = 0; nt < 8; nt++) {
            P01[nt] = ex2h2(cvt2h(fmaf(S[nt][1], C, -mc0), fmaf(S[nt][0], C, -mc0)));
            P23[nt] = ex2h2(cvt2h(fmaf(S[nt][3], C, -mc1), fmaf(S[nt][2], C, -mc1)));
        }

        uint32_t s01 = hadd2u(hadd2u(hadd2u(P01[0], P01[1]), hadd2u(P01[2], P01[3])),
                              hadd2u(hadd2u(P01[4], P01[5]), hadd2u(P01[6], P01[7])));
        uint32_t s23 = hadd2u(hadd2u(hadd2u(P23[0], P23[1]), hadd2u(P23[2], P23[3])),
                              hadd2u(hadd2u(P23[4], P23[5]), hadd2u(P23[6], P23[7])));
        float rs0 = h2sumf(s01), rs1 = h2sumf(s23);
        rs0 += __shfl_xor_sync(0xffffffffu, rs0, 1);
        rs0 += __shfl_xor_sync(0xffffffffu, rs0, 2);
        rs1 += __shfl_xor_sync(0xffffffffu, rs1, 1);
        rs1 += __shfl_xor_sync(0xffffffffu, rs1, 2);
        l0 = l0 * corr0 + rs0;
        l1 = l1 * corr1 + rs1;

#pragma unroll
        for (int nt = 0; nt < 8; nt++) {
            O[nt][0] *= corr0; O[nt][1] *= corr0;
            O[nt][2] *= corr1; O[nt][3] *= corr1;
        }

#pragma unroll
        for (int nt = 0; nt < 8; nt++) {
            uint32_t bv[8];
            uint32_t va = vbase + ((nt * 8) << 1);
            ldm4t(bv,     va);
            ldm4t(bv + 4, va + ((32 * 72) << 1));
#pragma unroll
            for (int ks = 0; ks < 4; ks++)
                mmah(O[nt], P01[2 * ks], P23[2 * ks], P01[2 * ks + 1], P23[2 * ks + 1],
                     bv[2 * ks], bv[2 * ks + 1]);
        }
    }

    float inv0 = 1.0f / l0, inv1 = 1.0f / l1;
    size_t cb = (size_t)bh * TKN * DK;
    int r0 = t0 + wq * 64 + wi * 16 + g;
#pragma unroll
    for (int nt = 0; nt < 8; nt++) {
        int col = nt * 8 + 2 * tg;
        *(__half2*)(g_ctxh + cb + (size_t)r0 * DK + col) =
            __floats2half2_rn(O[nt][0] * inv0, O[nt][1] * inv0);
        *(__half2*)(g_ctxh + cb + (size_t)(r0 + 8) * DK + col) =
            __floats2half2_rn(O[nt][2] * inv1, O[nt][3] * inv1);
    }
}

// ---------------------------------------------------------------------------
// Kernel 3: output projection (128x128, 4-stage ring, distance 2, 1 sync).
// All 12 fragment loads hoisted to iteration top.
// ---------------------------------------------------------------------------
#define O_BH 5120
#define O_STAGE_B 20480

__global__ __launch_bounds__(256, 2) void outproj_kernel(
    const float* __restrict__ bo, float* __restrict__ out)
{
    extern __shared__ __half sdyn2[];
    __shared__ float sBias[128];

    int j0 = blockIdx.x * 128;
    int m0 = blockIdx.y * 128;

    int tid = threadIdx.x;
    int lane = tid & 31, w = tid >> 5;
    int wm = w & 3, wn = w >> 2;
    int g = lane >> 2, tg = lane & 3;

    if (tid < 128) sBias[tid] = bo[j0 + tid];

    uint32_t sb0 = cvta_s(sdyn2);
    int xrow = tid >> 2, xseg = tid & 3;

    float acc[2][8][4];
#pragma unroll
    for (int mt = 0; mt < 2; mt++)
#pragma unroll
        for (int nt = 0; nt < 8; nt++)
#pragma unroll
            for (int q = 0; q < 4; q++) acc[mt][nt][q] = 0.0f;

    int arow = wm * 32 + ((lane >> 3) & 1) * 8 + (lane & 7);
    int acol = (lane >> 4) * 8;
    uint32_t a_off = (uint32_t)(arow * 40 + acol) * 2;
    uint32_t k_off = (uint32_t)((lane & 7) * 40 + (lane >> 3) * 8) * 2;

    auto stage = [&](int s, int d0) {
        uint32_t base = sb0 + s * O_STAGE_B;
#pragma unroll
        for (int i = 0; i < 2; i++) {
            int r = xrow + i * 64;
            uint32_t dof = (uint32_t)(r * 40 + xseg * 8) * 2;
            cp16(base + dof,            g_ctxh + (size_t)(m0 + r) * DM + d0 + xseg * 8);
            cp16(base + O_BH * 2 + dof, g_Wof  + (size_t)(j0 + r) * DM + d0 + xseg * 8);
        }
        cpcommit();
    };

    stage(0, 0); stage(1, 32);

    const int nIter = DM / 32;
    for (int it = 0; it < nIter; it++) {
        if (it + 2 < nIter) { stage((it + 2) & 3, (it + 2) * 32); cpwait<2>(); }
        else if (it + 1 < nIter) cpwait<1>();
        else cpwait<0>();
        __syncthreads();

        uint32_t base = sb0 + (it & 3) * O_STAGE_B;
        uint32_t abh = base + a_off;
        uint32_t kbh = base + O_BH * 2 + k_off;

        uint32_t AH[2][2][4];
#pragma unroll
        for (int mt = 0; mt < 2; mt++)
#pragma unroll
            for (int ks = 0; ks < 2; ks++)
                ldm4(AH[mt][ks], abh + (mt * 16 * 40 + ks * 16) * 2);

        uint32_t BH[8][4];
#pragma unroll
        for (int nt = 0; nt < 8; nt++)
            ldm4(BH[nt], kbh + ((wn * 64 + nt * 8) * 40) * 2);

#pragma unroll
        for (int nt = 0; nt < 8; nt++)
#pragma unroll
            for (int ks = 0; ks < 2; ks++)
#pragma unroll
                for (int mt = 0; mt < 2; mt++)
                    mmah(acc[mt][nt],
                         AH[mt][ks][0], AH[mt][ks][1], AH[mt][ks][2], AH[mt][ks][3],
                         BH[nt][2 * ks], BH[nt][2 * ks + 1]);
    }

#pragma unroll
    for (int mt = 0; mt < 2; mt++) {
        int r0 = m0 + wm * 32 + mt * 16 + g;
#pragma unroll
        for (int nt = 0; nt < 8; nt++) {
            int cl = wn * 64 + nt * 8 + 2 * tg;
            float b0v = sBias[cl], b1v = sBias[cl + 1];
            *(float2*)(out + (size_t)r0 * DM + j0 + cl) =
                make_float2(acc[mt][nt][0] + b0v, acc[mt][nt][1] + b1v);
            *(float2*)(out + (size_t)(r0 + 8) * DM + j0 + cl) =
                make_float2(acc[mt][nt][2] + b0v, acc[mt][nt][3] + b1v);
        }
    }
}

// ---------------------------------------------------------------------------
extern "C" void kernel_launch(void* const* d_in, const int* in_sizes, int n_in,
                              void* d_out, int out_size)
{
    const float* Q  = (const float*)d_in[0];
    const float* K  = (const float*)d_in[1];
    const float* V  = (const float*)d_in[2];
    const float* Wq = (const float*)d_in[3];
    const float* bq = (const float*)d_in[4];
    const float* Wk = (const float*)d_in[5];
    const float* bk = (const float*)d_in[6];
    const float* Wv = (const float*)d_in[7];
    const float* bv = (const float*)d_in[8];
    const float* Wo = (const float*)d_in[9];
    const float* bo = (const float*)d_in[10];
    float* out = (float*)d_out;

    cudaFuncSetAttribute(proj_kernel, cudaFuncAttributeMaxDynamicSharedMemorySize, 4 * P_STAGE_B);
    cudaFuncSetAttribute(outproj_kernel, cudaFuncAttributeMaxDynamicSharedMemorySize, 4 * O_STAGE_B);

    dim3 gs(128, 7);
    split_kernel<<<gs, 256>>>(Q, K, V, Wq, Wk, Wv, Wo);

    dim3 g1(TKN / 128, B_SZ * 8, 3);
    proj_kernel<<<g1, 256, 4 * P_STAGE_B>>>(bq, bk, bv);

    dim3 g2(TKN / 128, B_SZ * HEADS);
    flash_kernel<<<g2, 256>>>();

    dim3 g3(DM / 128, (B_SZ * TKN) / 128);
    outproj_kernel<<<g3, 256, 4 * O_STAGE_B>>>(bo, out);
}

// round 14
// speedup vs baseline: 1.2432x; 1.0211x over previous
#include <cuda_runtime.h>
#include <cuda_fp16.h>
#include <cstdint>

#define B_SZ  2
#define HEADS 16
#define TKN   2048
#define DM    1024
#define DK    64

// ---- fp16 mma / ldmatrix / f16x2 helpers ----
__device__ __forceinline__ uint32_t cvta_s(const void* p) {
    return (uint32_t)__cvta_generic_to_shared(p);
}
__device__ __forceinline__ void ldm4(uint32_t* r, uint32_t a) {
    asm volatile("ldmatrix.sync.aligned.m8n8.x4.shared.b16 {%0,%1,%2,%3},[%4];"
        : "=r"(r[0]), "=r"(r[1]), "=r"(r[2]), "=r"(r[3]) : "r"(a));
}
__device__ __forceinline__ void ldm4t(uint32_t* r, uint32_t a) {
    asm volatile("ldmatrix.sync.aligned.m8n8.x4.trans.shared.b16 {%0,%1,%2,%3},[%4];"
        : "=r"(r[0]), "=r"(r[1]), "=r"(r[2]), "=r"(r[3]) : "r"(a));
}
__device__ __forceinline__ void mmah(float* d, uint32_t a0, uint32_t a1, uint32_t a2,
                                     uint32_t a3, uint32_t b0, uint32_t b1) {
    asm("mma.sync.aligned.m16n8k16.row.col.f32.f16.f16.f32 "
        "{%0,%1,%2,%3},{%4,%5,%6,%7},{%8,%9},{%0,%1,%2,%3};"
        : "+f"(d[0]), "+f"(d[1]), "+f"(d[2]), "+f"(d[3])
        : "r"(a0), "r"(a1), "r"(a2), "r"(a3), "r"(b0), "r"(b1));
}
__device__ __forceinline__ uint32_t cvt2h(float hi, float lo) {
    uint32_t d; asm("cvt.rn.f16x2.f32 %0, %1, %2;" : "=r"(d) : "f"(hi), "f"(lo)); return d;
}
__device__ __forceinline__ uint32_t ex2h2(uint32_t x) {
    uint32_t d; asm("ex2.approx.f16x2 %0, %1;" : "=r"(d) : "r"(x)); return d;
}
__device__ __forceinline__ float ex2f(float x) {
    float d; asm("ex2.approx.ftz.f32 %0, %1;" : "=f"(d) : "f"(x)); return d;
}
__device__ __forceinline__ uint32_t hadd2u(uint32_t a, uint32_t b) {
    uint32_t d; asm("add.rn.f16x2 %0, %1, %2;" : "=r"(d) : "r"(a), "r"(b)); return d;
}
__device__ __forceinline__ float h2sumf(uint32_t h) {
    __half2 v = *(__half2*)&h;
    return __low2float(v) + __high2float(v);
}
// cp.async 16B, L2-only (.cg) — staged data is consumed once; keep L1 for LDSM
__device__ __forceinline__ void cp16(uint32_t d, const void* s) {
    asm volatile("cp.async.cg.shared.global [%0], [%1], 16;" :: "r"(d), "l"(s));
}
__device__ __forceinline__ void cpcommit() { asm volatile("cp.async.commit_group;"); }
template <int N>
__device__ __forceinline__ void cpwait() {
    asm volatile("cp.async.wait_group %0;" :: "n"(N));
}

// ---- device-global scratch (no allocation) ----
__device__ __half g_Xf[3][B_SZ * TKN * DM];      // f16(X) for Q,K,V inputs
__device__ __half g_Wf[3][HEADS * DM * DK];      // f16(W) for Wq,Wk,Wv
__device__ __half g_Wof[DM * DM];                // f16(Wo)
__device__ __half g_Qh[B_SZ * HEADS * TKN * DK]; // pre-scaled by 1/8
__device__ __half g_Kh[B_SZ * HEADS * TKN * DK];
__device__ __half g_Vh[B_SZ * HEADS * TKN * DK];
__device__ __half g_ctxh[B_SZ * HEADS * TKN * DK];

// ---------------------------------------------------------------------------
// Kernel 0: fused f32 -> f16 convert for all 7 tensors (blockIdx.y selects).
// 2 float4 per thread per iteration for higher MLP; 256 CTAs per tensor.
// ---------------------------------------------------------------------------
__global__ __launch_bounds__(256) void split_kernel(
    const float* __restrict__ Q, const float* __restrict__ K, const float* __restrict__ V,
    const float* __restrict__ Wq, const float* __restrict__ Wk, const float* __restrict__ Wv,
    const float* __restrict__ Wo)
{
    int y = blockIdx.y;
    const float* src; __half* dst; int n4;
    switch (y) {
        case 0: src = Q;  dst = g_Xf[0]; n4 = (B_SZ * TKN * DM) / 4; break;
        case 1: src = K;  dst = g_Xf[1]; n4 = (B_SZ * TKN * DM) / 4; break;
        case 2: src = V;  dst = g_Xf[2]; n4 = (B_SZ * TKN * DM) / 4; break;
        case 3: src = Wq; dst = g_Wf[0]; n4 = (HEADS * DM * DK) / 4; break;
        case 4: src = Wk; dst = g_Wf[1]; n4 = (HEADS * DM * DK) / 4; break;
        case 5: src = Wv; dst = g_Wf[2]; n4 = (HEADS * DM * DK) / 4; break;
        default: src = Wo; dst = g_Wof;  n4 = (DM * DM) / 4; break;
    }
    int tid0 = blockIdx.x * blockDim.x + threadIdx.x;
    int stride = gridDim.x * blockDim.x;
    for (int i = tid0 * 2; i < n4; i += stride * 2) {
        float4 v0 = ((const float4*)src)[i];
        ((__half2*)dst)[2 * i]     = __floats2half2_rn(v0.x, v0.y);
        ((__half2*)dst)[2 * i + 1] = __floats2half2_rn(v0.z, v0.w);
        if (i + 1 < n4) {
            float4 v1 = ((const float4*)src)[i + 1];
            ((__half2*)dst)[2 * i + 2] = __floats2half2_rn(v1.x, v1.y);
            ((__half2*)dst)[2 * i + 3] = __floats2half2_rn(v1.z, v1.w);
        }
    }
}

// ---------------------------------------------------------------------------
// Kernel 1: QKV projections. CTA 128(t) x 128(2 heads), 256 thr, 8 warps
// (4M x 2N), warp tile 32x64. 4-stage ring, distance 2 -> one sync/iter.
// All 12 fragment loads hoisted to iteration top.
// ---------------------------------------------------------------------------
#define P_W   5120
#define P_STAGE_B 18944

__global__ __launch_bounds__(256, 2) void proj_kernel(
    const float* __restrict__ bq, const float* __restrict__ bk, const float* __restrict__ bv)
{
    extern __shared__ __half sdyn[];
    __shared__ float sBias[128];

    int z = blockIdx.z;
    const float* bias = (z == 0) ? bq : (z == 1) ? bk : bv;
    __half* out = (z == 0) ? g_Qh : (z == 1) ? g_Kh : g_Vh;
    float oscale = (z == 0) ? 0.125f : 1.0f;

    int y = blockIdx.y;
    int b = y >> 3, h0 = (y & 7) * 2;
    int t0 = blockIdx.x * 128;

    const __half* Xp = g_Xf[z] + ((size_t)b * TKN + t0) * DM;
    const __half* Wp = g_Wf[z] + (size_t)h0 * DM * DK;

    int tid = threadIdx.x;
    int lane = tid & 31, w = tid >> 5;
    int wm = w & 3, wn = w >> 2;
    int g = lane >> 2, tg = lane & 3;

    if (tid < 128) sBias[tid] = bias[h0 * DK + tid];

    uint32_t sb0 = cvta_s(sdyn);

    int xrow = tid >> 2, xseg = tid & 3;
    int wrow_c = tid >> 4, wcol_c = (tid & 15) * 8;
    size_t wso = (size_t)(wcol_c >= 64 ? DM * DK : 0) + (size_t)wrow_c * DK + (wcol_c & 63);

    float acc[2][8][4];
#pragma unroll
    for (int mt = 0; mt < 2; mt++)
#pragma unroll
        for (int nt = 0; nt < 8; nt++)
#pragma unroll
            for (int q = 0; q < 4; q++) acc[mt][nt][q] = 0.0f;

    int arow = wm * 32 + ((lane >> 3) & 1) * 8 + (lane & 7);
    int acol = (lane >> 4) * 8;
    uint32_t a_off = (uint32_t)(arow * 40 + acol) * 2;
    uint32_t w_off = ((uint32_t)((lane >> 3) * 8 + (lane & 7)) * 136) * 2;

    auto stage = [&](int s, int d0) {
        uint32_t base = sb0 + s * P_STAGE_B;
#pragma unroll
        for (int i = 0; i < 2; i++) {
            int r = xrow + i * 64;
            cp16(base + (uint32_t)(r * 40 + xseg * 8) * 2,
                 Xp + (size_t)r * DM + d0 + xseg * 8);
        }
#pragma unroll
        for (int i = 0; i < 2; i++) {
            int r = wrow_c + i * 16;
            cp16(base + P_W * 2 + (uint32_t)(r * 136 + wcol_c) * 2,
                 Wp + wso + (size_t)(d0 + i * 16) * DK);
        }
        cpcommit();
    };

    stage(0, 0); stage(1, 32);

    const int nIter = DM / 32;
    for (int it = 0; it < nIter; it++) {
        if (it + 2 < nIter) { stage((it + 2) & 3, (it + 2) * 32); cpwait<2>(); }
        else if (it + 1 < nIter) cpwait<1>();
        else cpwait<0>();
        __syncthreads();

        uint32_t base = sb0 + (it & 3) * P_STAGE_B;
        uint32_t abh = base + a_off;
        uint32_t wbh = base + P_W * 2 + w_off;

        uint32_t AH[2][2][4];
#pragma unroll
        for (int mt = 0; mt < 2; mt++)
#pragma unroll
            for (int ks = 0; ks < 2; ks++)
                ldm4(AH[mt][ks], abh + (mt * 16 * 40 + ks * 16) * 2);

        uint32_t BH[8][4];
#pragma unroll
        for (int nt = 0; nt < 8; nt++)
            ldm4t(BH[nt], wbh + (wn * 64 + nt * 8) * 2);

#pragma unroll
        for (int nt = 0; nt < 8; nt++)
#pragma unroll
            for (int ks = 0; ks < 2; ks++)
#pragma unroll
                for (int mt = 0; mt < 2; mt++)
                    mmah(acc[mt][nt],
                         AH[mt][ks][0], AH[mt][ks][1], AH[mt][ks][2], AH[mt][ks][3],
                         BH[nt][2 * ks], BH[nt][2 * ks + 1]);
    }

    __half* outh = out + ((size_t)(b * HEADS + h0 + wn) * TKN + t0) * DK;
#pragma unroll
    for (int mt = 0; mt < 2; mt++) {
        int r0 = wm * 32 + mt * 16 + g;
#pragma unroll
        for (int nt = 0; nt < 8; nt++) {
            int cl = nt * 8 + 2 * tg;
            float b0v = sBias[wn * 64 + cl], b1v = sBias[wn * 64 + cl + 1];
            *(__half2*)(outh + (size_t)r0 * DK + cl) =
                __floats2half2_rn((acc[mt][nt][0] + b0v) * oscale, (acc[mt][nt][1] + b1v) * oscale);
            *(__half2*)(outh + (size_t)(r0 + 8) * DK + cl) =
                __floats2half2_rn((acc[mt][nt][2] + b0v) * oscale, (acc[mt][nt][3] + b1v) * oscale);
        }
    }
}

// ---------------------------------------------------------------------------
// Kernel 2: flash attention (measured-best structure): 128 queries / 8 warps
// per CTA, K/V double-buffered via cp.async.
// ---------------------------------------------------------------------------
__global__ __launch_bounds__(256) void flash_kernel()
{
    __shared__ __half Qs[128][72];
    __shared__ __half Ks[2][64][72];
    __shared__ __half Vs[2][64][72];

    const float C = 1.4426950408889634f;
    const uint32_t BUFB = 64 * 72 * 2;

    int bh = blockIdx.y;
    int t0 = blockIdx.x * 128;
    const __half* Qp = g_Qh + (size_t)bh * TKN * DK;
    const __half* Kp = g_Kh + (size_t)bh * TKN * DK;
    const __half* Vp = g_Vh + (size_t)bh * TKN * DK;

    int tid = threadIdx.x;
    int lane = tid & 31, w = tid >> 5;
    int wq = w >> 2, wi = w & 3;
    int g = lane >> 2, tg = lane & 3;

    uint32_t ksb = cvta_s(Ks), vsb = cvta_s(Vs);

    auto stagekv = [&](int buf, int s0) {
#pragma unroll
        for (int i = 0; i < 2; i++) {
            int idx = i * 256 + tid;
            int r = idx >> 3, c = idx & 7;
            uint32_t dof = (uint32_t)(r * 72 + c * 8) * 2;
            cp16(ksb + buf * BUFB + dof, Kp + (size_t)(s0 + r) * DK + c * 8);
            cp16(vsb + buf * BUFB + dof, Vp + (size_t)(s0 + r) * DK + c * 8);
        }
        cpcommit();
    };

    stagekv(0, 0);

#pragma unroll
    for (int i = 0; i < 4; i++) {
        int idx = i * 256 + tid;
        int r = idx >> 3, c = idx & 7;
        *(uint4*)&Qs[r][c * 8] = *(const uint4*)(Qp + (size_t)(t0 + r) * DK + c * 8);
    }
    __syncthreads();

    uint32_t Qa[4][4];
    {
        int qrow = wq * 64 + wi * 16 + ((lane >> 3) & 1) * 8 + (lane & 7);
        int qcol = (lane >> 4) * 8;
        uint32_t qbase = cvta_s(&Qs[qrow][qcol]);
#pragma unroll
        for (int ks = 0; ks < 4; ks++) ldm4(Qa[ks], qbase + ks * 32);
    }

    uint32_t k_off = (((lane & 7) * 72 + (lane >> 3) * 8) << 1);
    uint32_t v_off = ((((lane >> 3) * 8 + (lane & 7)) * 72) << 1);

    float m0 = -1e30f, m1 = -1e30f, l0 = 0.0f, l1 = 0.0f;
    float O[8][4];
#pragma unroll
    for (int nt = 0; nt < 8; nt++)
#pragma unroll
        for (int q = 0; q < 4; q++) O[nt][q] = 0.0f;

    const int nCh = TKN / 64;
    for (int it = 0; it < nCh; it++) {
        if (it > 0) __syncthreads();
        if (it + 1 < nCh) { stagekv((it + 1) & 1, (it + 1) * 64); cpwait<1>(); }
        else              { cpwait<0>(); }
        __syncthreads();

        uint32_t kbase = ksb + (it & 1) * BUFB + k_off;
        uint32_t vbase = vsb + (it & 1) * BUFB + v_off;

        float S[8][4];
#pragma unroll
        for (int nt = 0; nt < 8; nt++) {
#pragma unroll
            for (int q = 0; q < 4; q++) S[nt][q] = 0.0f;
            uint32_t bk[8];
            uint32_t ka = kbase + ((nt * 8 * 72) << 1);
            ldm4(bk,     ka);
            ldm4(bk + 4, ka + 64);
#pragma unroll
            for (int ks = 0; ks < 4; ks++)
                mmah(S[nt], Qa[ks][0], Qa[ks][1], Qa[ks][2], Qa[ks][3],
                     bk[2 * ks], bk[2 * ks + 1]);
        }

        float mx0 = fmaxf(S[0][0], S[0][1]);
        float mx1 = fmaxf(S[0][2], S[0][3]);
#pragma unroll
        for (int nt = 1; nt < 8; nt++) {
            mx0 = fmaxf(mx0, fmaxf(S[nt][0], S[nt][1]));
            mx1 = fmaxf(mx1, fmaxf(S[nt][2], S[nt][3]));
        }
        mx0 = fmaxf(mx0, __shfl_xor_sync(0xffffffffu, mx0, 1));
        mx0 = fmaxf(mx0, __shfl_xor_sync(0xffffffffu, mx0, 2));
        mx1 = fmaxf(mx1, __shfl_xor_sync(0xffffffffu, mx1, 1));
        mx1 = fmaxf(mx1, __shfl_xor_sync(0xffffffffu, mx1, 2));

        float mn0 = fmaxf(m0, mx0), mn1 = fmaxf(m1, mx1);
        float corr0 = ex2f((m0 - mn0) * C);
        float corr1 = ex2f((m1 - mn1) * C);
        m0 = mn0; m1 = mn1;
        float mc0 = mn0 * C, mc1 = mn1 * C;

        uint32_t P01[8], P23[8];
#pragma unroll
        for (int nt = 0; nt < 8; nt++) {
            P01[nt] = ex2h2(cvt2h(fmaf(S[nt][1], C, -mc0), fmaf(S[nt][0], C, -mc0)));
            P23[nt] = ex2h2(cvt2h(fmaf(S[nt][3], C, -mc1), fmaf(S[nt][2], C, -mc1)));
        }

        uint32_t s01 = hadd2u(hadd2u(hadd2u(P01[0], P01[1]), hadd2u(P01[2], P01[3])),
                              hadd2u(hadd2u(P01[4], P01[5]), hadd2u(P01[6], P01[7])));
        uint32_t s23 = hadd2u(hadd2u(hadd2u(P23[0], P23[1]), hadd2u(P23[2], P23[3])),
                              hadd2u(hadd2u(P23[4], P23[5]), hadd2u(P23[6], P23[7])));
        float rs0 = h2sumf(s01), rs1 = h2sumf(s23);
        rs0 += __shfl_xor_sync(0xffffffffu, rs0, 1);
        rs0 += __shfl_xor_sync(0xffffffffu, rs0, 2);
        rs1 += __shfl_xor_sync(0xffffffffu, rs1, 1);
        rs1 += __shfl_xor_sync(0xffffffffu, rs1, 2);
        l0 = l0 * corr0 + rs0;
        l1 = l1 * corr1 + rs1;

#pragma unroll
        for (int nt = 0; nt < 8; nt++) {
            O[nt][0] *= corr0; O[nt][1] *= corr0;
            O[nt][2] *= corr1; O[nt][3] *= corr1;
        }

#pragma unroll
        for (int nt = 0; nt < 8; nt++) {
            uint32_t bv[8];
            uint32_t va = vbase + ((nt * 8) << 1);
            ldm4t(bv,     va);
            ldm4t(bv + 4, va + ((32 * 72) << 1));
#pragma unroll
            for (int ks = 0; ks < 4; ks++)
                mmah(O[nt], P01[2 * ks], P23[2 * ks], P01[2 * ks + 1], P23[2 * ks + 1],
                     bv[2 * ks], bv[2 * ks + 1]);
        }
    }

    float inv0 = 1.0f / l0, inv1 = 1.0f / l1;
    size_t cb = (size_t)bh * TKN * DK;
    int r0 = t0 + wq * 64 + wi * 16 + g;
#pragma unroll
    for (int nt = 0; nt < 8; nt++) {
        int col = nt * 8 + 2 * tg;
        *(__half2*)(g_ctxh + cb + (size_t)r0 * DK + col) =
            __floats2half2_rn(O[nt][0] * inv0, O[nt][1] * inv0);
        *(__half2*)(g_ctxh + cb + (size_t)(r0 + 8) * DK + col) =
            __floats2half2_rn(O[nt][2] * inv1, O[nt][3] * inv1);
    }
}

// ---------------------------------------------------------------------------
// Kernel 3: output projection (128x128, 4-stage ring, distance 2, 1 sync).
// All 12 fragment loads hoisted to iteration top.
// ---------------------------------------------------------------------------
#define O_BH 5120
#define O_STAGE_B 20480

__global__ __launch_bounds__(256, 2) void outproj_kernel(
    const float* __restrict__ bo, float* __restrict__ out)
{
    extern __shared__ __half sdyn2[];
    __shared__ float sBias[128];

    int j0 = blockIdx.x * 128;
    int m0 = blockIdx.y * 128;

    int tid = threadIdx.x;
    int lane = tid & 31, w = tid >> 5;
    int wm = w & 3, wn = w >> 2;
    int g = lane >> 2, tg = lane & 3;

    if (tid < 128) sBias[tid] = bo[j0 + tid];

    uint32_t sb0 = cvta_s(sdyn2);
    int xrow = tid >> 2, xseg = tid & 3;

    float acc[2][8][4];
#pragma unroll
    for (int mt = 0; mt < 2; mt++)
#pragma unroll
        for (int nt = 0; nt < 8; nt++)
#pragma unroll
            for (int q = 0; q < 4; q++) acc[mt][nt][q] = 0.0f;

    int arow = wm * 32 + ((lane >> 3) & 1) * 8 + (lane & 7);
    int acol = (lane >> 4) * 8;
    uint32_t a_off = (uint32_t)(arow * 40 + acol) * 2;
    uint32_t k_off = (uint32_t)((lane & 7) * 40 + (lane >> 3) * 8) * 2;

    auto stage = [&](int s, int d0) {
        uint32_t base = sb0 + s * O_STAGE_B;
#pragma unroll
        for (int i = 0; i < 2; i++) {
            int r = xrow + i * 64;
            uint32_t dof = (uint32_t)(r * 40 + xseg * 8) * 2;
            cp16(base + dof,            g_ctxh + (size_t)(m0 + r) * DM + d0 + xseg * 8);
            cp16(base + O_BH * 2 + dof, g_Wof  + (size_t)(j0 + r) * DM + d0 + xseg * 8);
        }
        cpcommit();
    };

    stage(0, 0); stage(1, 32);

    const int nIter = DM / 32;
    for (int it = 0; it < nIter; it++) {
        if (it + 2 < nIter) { stage((it + 2) & 3, (it + 2) * 32); cpwait<2>(); }
        else if (it + 1 < nIter) cpwait<1>();
        else cpwait<0>();
        __syncthreads();

        uint32_t base = sb0 + (it & 3) * O_STAGE_B;
        uint32_t abh = base + a_off;
        uint32_t kbh = base + O_BH * 2 + k_off;

        uint32_t AH[2][2][4];
#pragma unroll
        for (int mt = 0; mt < 2; mt++)
#pragma unroll
            for (int ks = 0; ks < 2; ks++)
                ldm4(AH[mt][ks], abh + (mt * 16 * 40 + ks * 16) * 2);

        uint32_t BH[8][4];
#pragma unroll
        for (int nt = 0; nt < 8; nt++)
            ldm4(BH[nt], kbh + ((wn * 64 + nt * 8) * 40) * 2);

#pragma unroll
        for (int nt = 0; nt < 8; nt++)
#pragma unroll
            for (int ks = 0; ks < 2; ks++)
#pragma unroll
                for (int mt = 0; mt < 2; mt++)
                    mmah(acc[mt][nt],
                         AH[mt][ks][0], AH[mt][ks][1], AH[mt][ks][2], AH[mt][ks][3],
                         BH[nt][2 * ks], BH[nt][2 * ks + 1]);
    }

#pragma unroll
    for (int mt = 0; mt < 2; mt++) {
        int r0 = m0 + wm * 32 + mt * 16 + g;
#pragma unroll
        for (int nt = 0; nt < 8; nt++) {
            int cl = wn * 64 + nt * 8 + 2 * tg;
            float b0v = sBias[cl], b1v = sBias[cl + 1];
            *(float2*)(out + (size_t)r0 * DM + j0 + cl) =
                make_float2(acc[mt][nt][0] + b0v, acc[mt][nt][1] + b1v);
            *(float2*)(out + (size_t)(r0 + 8) * DM + j0 + cl) =
                make_float2(acc[mt][nt][2] + b0v, acc[mt][nt][3] + b1v);
        }
    }
}

// ---------------------------------------------------------------------------
extern "C" void kernel_launch(void* const* d_in, const int* in_sizes, int n_in,
                              void* d_out, int out_size)
{
    const float* Q  = (const float*)d_in[0];
    const float* K  = (const float*)d_in[1];
    const float* V  = (const float*)d_in[2];
    const float* Wq = (const float*)d_in[3];
    const float* bq = (const float*)d_in[4];
    const float* Wk = (const float*)d_in[5];
    const float* bk = (const float*)d_in[6];
    const float* Wv = (const float*)d_in[7];
    const float* bv = (const float*)d_in[8];
    const float* Wo = (const float*)d_in[9];
    const float* bo = (const float*)d_in[10];
    float* out = (float*)d_out;

    cudaFuncSetAttribute(proj_kernel, cudaFuncAttributeMaxDynamicSharedMemorySize, 4 * P_STAGE_B);
    cudaFuncSetAttribute(outproj_kernel, cudaFuncAttributeMaxDynamicSharedMemorySize, 4 * O_STAGE_B);

    dim3 gs(256, 7);
    split_kernel<<<gs, 256>>>(Q, K, V, Wq, Wk, Wv, Wo);

    dim3 g1(TKN / 128, B_SZ * 8, 3);
    proj_kernel<<<g1, 256, 4 * P_STAGE_B>>>(bq, bk, bv);

    dim3 g2(TKN / 128, B_SZ * HEADS);
    flash_kernel<<<g2, 256>>>();

    dim3 g3(DM / 128, (B_SZ * TKN) / 128);
    outproj_kernel<<<g3, 256, 4 * O_STAGE_B>>>(bo, out);
}

// round 15
// speedup vs baseline: 1.2504x; 1.0058x over previous
#include <cuda_runtime.h>
#include <cuda_fp16.h>
#include <cstdint>

#define B_SZ  2
#define HEADS 16
#define TKN   2048
#define DM    1024
#define DK    64

// ---- fp16 mma / ldmatrix / f16x2 helpers ----
__device__ __forceinline__ uint32_t cvta_s(const void* p) {
    return (uint32_t)__cvta_generic_to_shared(p);
}
__device__ __forceinline__ void ldm4(uint32_t* r, uint32_t a) {
    asm volatile("ldmatrix.sync.aligned.m8n8.x4.shared.b16 {%0,%1,%2,%3},[%4];"
        : "=r"(r[0]), "=r"(r[1]), "=r"(r[2]), "=r"(r[3]) : "r"(a));
}
__device__ __forceinline__ void ldm4t(uint32_t* r, uint32_t a) {
    asm volatile("ldmatrix.sync.aligned.m8n8.x4.trans.shared.b16 {%0,%1,%2,%3},[%4];"
        : "=r"(r[0]), "=r"(r[1]), "=r"(r[2]), "=r"(r[3]) : "r"(a));
}
__device__ __forceinline__ void mmah(float* d, uint32_t a0, uint32_t a1, uint32_t a2,
                                     uint32_t a3, uint32_t b0, uint32_t b1) {
    asm("mma.sync.aligned.m16n8k16.row.col.f32.f16.f16.f32 "
        "{%0,%1,%2,%3},{%4,%5,%6,%7},{%8,%9},{%0,%1,%2,%3};"
        : "+f"(d[0]), "+f"(d[1]), "+f"(d[2]), "+f"(d[3])
        : "r"(a0), "r"(a1), "r"(a2), "r"(a3), "r"(b0), "r"(b1));
}
__device__ __forceinline__ uint32_t cvt2h(float hi, float lo) {
    uint32_t d; asm("cvt.rn.f16x2.f32 %0, %1, %2;" : "=r"(d) : "f"(hi), "f"(lo)); return d;
}
__device__ __forceinline__ uint32_t ex2h2(uint32_t x) {
    uint32_t d; asm("ex2.approx.f16x2 %0, %1;" : "=r"(d) : "r"(x)); return d;
}
__device__ __forceinline__ float ex2f(float x) {
    float d; asm("ex2.approx.ftz.f32 %0, %1;" : "=f"(d) : "f"(x)); return d;
}
__device__ __forceinline__ uint32_t hadd2u(uint32_t a, uint32_t b) {
    uint32_t d; asm("add.rn.f16x2 %0, %1, %2;" : "=r"(d) : "r"(a), "r"(b)); return d;
}
__device__ __forceinline__ float h2sumf(uint32_t h) {
    __half2 v = *(__half2*)&h;
    return __low2float(v) + __high2float(v);
}
// cp.async 16B, L2-only (.cg) — staged data is consumed once; keep L1 for LDSM
__device__ __forceinline__ void cp16(uint32_t d, const void* s) {
    asm volatile("cp.async.cg.shared.global [%0], [%1], 16;" :: "r"(d), "l"(s));
}
__device__ __forceinline__ void cpcommit() { asm volatile("cp.async.commit_group;"); }
template <int N>
__device__ __forceinline__ void cpwait() {
    asm volatile("cp.async.wait_group %0;" :: "n"(N));
}

// ---- device-global scratch (no allocation) ----
__device__ __half g_Xf[3][B_SZ * TKN * DM];      // f16(X) for Q,K,V inputs
__device__ __half g_Wf[3][HEADS * DM * DK];      // f16(W) for Wq,Wk,Wv
__device__ __half g_Wof[DM * DM];                // f16(Wo)
__device__ __half g_Qh[B_SZ * HEADS * TKN * DK]; // pre-scaled by 1/8
__device__ __half g_Kh[B_SZ * HEADS * TKN * DK];
__device__ __half g_Vh[B_SZ * HEADS * TKN * DK];
__device__ __half g_ctxh[B_SZ * HEADS * TKN * DK];

// ---------------------------------------------------------------------------
// Kernel 0: fused f32 -> f16 convert for all 7 tensors (blockIdx.y selects).
// ---------------------------------------------------------------------------
__global__ __launch_bounds__(256) void split_kernel(
    const float* __restrict__ Q, const float* __restrict__ K, const float* __restrict__ V,
    const float* __restrict__ Wq, const float* __restrict__ Wk, const float* __restrict__ Wv,
    const float* __restrict__ Wo)
{
    int y = blockIdx.y;
    const float* src; __half* dst; int n4;
    switch (y) {
        case 0: src = Q;  dst = g_Xf[0]; n4 = (B_SZ * TKN * DM) / 4; break;
        case 1: src = K;  dst = g_Xf[1]; n4 = (B_SZ * TKN * DM) / 4; break;
        case 2: src = V;  dst = g_Xf[2]; n4 = (B_SZ * TKN * DM) / 4; break;
        case 3: src = Wq; dst = g_Wf[0]; n4 = (HEADS * DM * DK) / 4; break;
        case 4: src = Wk; dst = g_Wf[1]; n4 = (HEADS * DM * DK) / 4; break;
        case 5: src = Wv; dst = g_Wf[2]; n4 = (HEADS * DM * DK) / 4; break;
        default: src = Wo; dst = g_Wof;  n4 = (DM * DM) / 4; break;
    }
    int tid0 = blockIdx.x * blockDim.x + threadIdx.x;
    int stride = gridDim.x * blockDim.x;
    for (int i = tid0 * 2; i < n4; i += stride * 2) {
        float4 v0 = ((const float4*)src)[i];
        ((__half2*)dst)[2 * i]     = __floats2half2_rn(v0.x, v0.y);
        ((__half2*)dst)[2 * i + 1] = __floats2half2_rn(v0.z, v0.w);
        if (i + 1 < n4) {
            float4 v1 = ((const float4*)src)[i + 1];
            ((__half2*)dst)[2 * i + 2] = __floats2half2_rn(v1.x, v1.y);
            ((__half2*)dst)[2 * i + 3] = __floats2half2_rn(v1.z, v1.w);
        }
    }
}

// ---------------------------------------------------------------------------
// Kernel 1: QKV projections (R14, frozen). 128x128, 8 warps, 4-stage ring,
// distance 2, hoisted fragment loads.
// ---------------------------------------------------------------------------
#define P_W   5120
#define P_STAGE_B 18944

__global__ __launch_bounds__(256, 2) void proj_kernel(
    const float* __restrict__ bq, const float* __restrict__ bk, const float* __restrict__ bv)
{
    extern __shared__ __half sdyn[];
    __shared__ float sBias[128];

    int z = blockIdx.z;
    const float* bias = (z == 0) ? bq : (z == 1) ? bk : bv;
    __half* out = (z == 0) ? g_Qh : (z == 1) ? g_Kh : g_Vh;
    float oscale = (z == 0) ? 0.125f : 1.0f;

    int y = blockIdx.y;
    int b = y >> 3, h0 = (y & 7) * 2;
    int t0 = blockIdx.x * 128;

    const __half* Xp = g_Xf[z] + ((size_t)b * TKN + t0) * DM;
    const __half* Wp = g_Wf[z] + (size_t)h0 * DM * DK;

    int tid = threadIdx.x;
    int lane = tid & 31, w = tid >> 5;
    int wm = w & 3, wn = w >> 2;
    int g = lane >> 2, tg = lane & 3;

    if (tid < 128) sBias[tid] = bias[h0 * DK + tid];

    uint32_t sb0 = cvta_s(sdyn);

    int xrow = tid >> 2, xseg = tid & 3;
    int wrow_c = tid >> 4, wcol_c = (tid & 15) * 8;
    size_t wso = (size_t)(wcol_c >= 64 ? DM * DK : 0) + (size_t)wrow_c * DK + (wcol_c & 63);

    float acc[2][8][4];
#pragma unroll
    for (int mt = 0; mt < 2; mt++)
#pragma unroll
        for (int nt = 0; nt < 8; nt++)
#pragma unroll
            for (int q = 0; q < 4; q++) acc[mt][nt][q] = 0.0f;

    int arow = wm * 32 + ((lane >> 3) & 1) * 8 + (lane & 7);
    int acol = (lane >> 4) * 8;
    uint32_t a_off = (uint32_t)(arow * 40 + acol) * 2;
    uint32_t w_off = ((uint32_t)((lane >> 3) * 8 + (lane & 7)) * 136) * 2;

    auto stage = [&](int s, int d0) {
        uint32_t base = sb0 + s * P_STAGE_B;
#pragma unroll
        for (int i = 0; i < 2; i++) {
            int r = xrow + i * 64;
            cp16(base + (uint32_t)(r * 40 + xseg * 8) * 2,
                 Xp + (size_t)r * DM + d0 + xseg * 8);
        }
#pragma unroll
        for (int i = 0; i < 2; i++) {
            int r = wrow_c + i * 16;
            cp16(base + P_W * 2 + (uint32_t)(r * 136 + wcol_c) * 2,
                 Wp + wso + (size_t)(d0 + i * 16) * DK);
        }
        cpcommit();
    };

    stage(0, 0); stage(1, 32);

    const int nIter = DM / 32;
    for (int it = 0; it < nIter; it++) {
        if (it + 2 < nIter) { stage((it + 2) & 3, (it + 2) * 32); cpwait<2>(); }
        else if (it + 1 < nIter) cpwait<1>();
        else cpwait<0>();
        __syncthreads();

        uint32_t base = sb0 + (it & 3) * P_STAGE_B;
        uint32_t abh = base + a_off;
        uint32_t wbh = base + P_W * 2 + w_off;

        uint32_t AH[2][2][4];
#pragma unroll
        for (int mt = 0; mt < 2; mt++)
#pragma unroll
            for (int ks = 0; ks < 2; ks++)
                ldm4(AH[mt][ks], abh + (mt * 16 * 40 + ks * 16) * 2);

        uint32_t BH[8][4];
#pragma unroll
        for (int nt = 0; nt < 8; nt++)
            ldm4t(BH[nt], wbh + (wn * 64 + nt * 8) * 2);

#pragma unroll
        for (int nt = 0; nt < 8; nt++)
#pragma unroll
            for (int ks = 0; ks < 2; ks++)
#pragma unroll
                for (int mt = 0; mt < 2; mt++)
                    mmah(acc[mt][nt],
                         AH[mt][ks][0], AH[mt][ks][1], AH[mt][ks][2], AH[mt][ks][3],
                         BH[nt][2 * ks], BH[nt][2 * ks + 1]);
    }

    __half* outh = out + ((size_t)(b * HEADS + h0 + wn) * TKN + t0) * DK;
#pragma unroll
    for (int mt = 0; mt < 2; mt++) {
        int r0 = wm * 32 + mt * 16 + g;
#pragma unroll
        for (int nt = 0; nt < 8; nt++) {
            int cl = nt * 8 + 2 * tg;
            float b0v = sBias[wn * 64 + cl], b1v = sBias[wn * 64 + cl + 1];
            *(__half2*)(outh + (size_t)r0 * DK + cl) =
                __floats2half2_rn((acc[mt][nt][0] + b0v) * oscale, (acc[mt][nt][1] + b1v) * oscale);
            *(__half2*)(outh + (size_t)(r0 + 8) * DK + cl) =
                __floats2half2_rn((acc[mt][nt][2] + b0v) * oscale, (acc[mt][nt][3] + b1v) * oscale);
        }
    }
}

// ---------------------------------------------------------------------------
// Kernel 2: flash attention. 128 queries / 8 warps per CTA, K/V
// double-buffered. NEW: pairwise-hoisted K and V fragment loads (2 groups'
// ldmatrix back-to-back, then 8 MMAs) — halves exposed LDSM latencies.
// ---------------------------------------------------------------------------
__global__ __launch_bounds__(256) void flash_kernel()
{
    __shared__ __half Qs[128][72];
    __shared__ __half Ks[2][64][72];
    __shared__ __half Vs[2][64][72];

    const float C = 1.4426950408889634f;
    const uint32_t BUFB = 64 * 72 * 2;

    int bh = blockIdx.y;
    int t0 = blockIdx.x * 128;
    const __half* Qp = g_Qh + (size_t)bh * TKN * DK;
    const __half* Kp = g_Kh + (size_t)bh * TKN * DK;
    const __half* Vp = g_Vh + (size_t)bh * TKN * DK;

    int tid = threadIdx.x;
    int lane = tid & 31, w = tid >> 5;
    int wq = w >> 2, wi = w & 3;
    int g = lane >> 2, tg = lane & 3;

    uint32_t ksb = cvta_s(Ks), vsb = cvta_s(Vs);

    auto stagekv = [&](int buf, int s0) {
#pragma unroll
        for (int i = 0; i < 2; i++) {
            int idx = i * 256 + tid;
            int r = idx >> 3, c = idx & 7;
            uint32_t dof = (uint32_t)(r * 72 + c * 8) * 2;
            cp16(ksb + buf * BUFB + dof, Kp + (size_t)(s0 + r) * DK + c * 8);
            cp16(vsb + buf * BUFB + dof, Vp + (size_t)(s0 + r) * DK + c * 8);
        }
        cpcommit();
    };

    stagekv(0, 0);

#pragma unroll
    for (int i = 0; i < 4; i++) {
        int idx = i * 256 + tid;
        int r = idx >> 3, c = idx & 7;
        *(uint4*)&Qs[r][c * 8] = *(const uint4*)(Qp + (size_t)(t0 + r) * DK + c * 8);
    }
    __syncthreads();

    uint32_t Qa[4][4];
    {
        int qrow = wq * 64 + wi * 16 + ((lane >> 3) & 1) * 8 + (lane & 7);
        int qcol = (lane >> 4) * 8;
        uint32_t qbase = cvta_s(&Qs[qrow][qcol]);
#pragma unroll
        for (int ks = 0; ks < 4; ks++) ldm4(Qa[ks], qbase + ks * 32);
    }

    uint32_t k_off = (((lane & 7) * 72 + (lane >> 3) * 8) << 1);
    uint32_t v_off = ((((lane >> 3) * 8 + (lane & 7)) * 72) << 1);

    float m0 = -1e30f, m1 = -1e30f, l0 = 0.0f, l1 = 0.0f;
    float O[8][4];
#pragma unroll
    for (int nt = 0; nt < 8; nt++)
#pragma unroll
        for (int q = 0; q < 4; q++) O[nt][q] = 0.0f;

    const int nCh = TKN / 64;
    for (int it = 0; it < nCh; it++) {
        if (it > 0) __syncthreads();
        if (it + 1 < nCh) { stagekv((it + 1) & 1, (it + 1) * 64); cpwait<1>(); }
        else              { cpwait<0>(); }
        __syncthreads();

        uint32_t kbase = ksb + (it & 1) * BUFB + k_off;
        uint32_t vbase = vsb + (it & 1) * BUFB + v_off;

        // S = Q K^T — pairwise-hoisted K fragments
        float S[8][4];
#pragma unroll
        for (int nt = 0; nt < 8; nt++)
#pragma unroll
            for (int q = 0; q < 4; q++) S[nt][q] = 0.0f;
#pragma unroll
        for (int np = 0; np < 4; np++) {
            int n0 = 2 * np, n1 = 2 * np + 1;
            uint32_t bk0[8], bk1[8];
            uint32_t ka0 = kbase + ((n0 * 8 * 72) << 1);
            uint32_t ka1 = kbase + ((n1 * 8 * 72) << 1);
            ldm4(bk0,     ka0);
            ldm4(bk0 + 4, ka0 + 64);
            ldm4(bk1,     ka1);
            ldm4(bk1 + 4, ka1 + 64);
#pragma unroll
            for (int ks = 0; ks < 4; ks++)
                mmah(S[n0], Qa[ks][0], Qa[ks][1], Qa[ks][2], Qa[ks][3],
                     bk0[2 * ks], bk0[2 * ks + 1]);
#pragma unroll
            for (int ks = 0; ks < 4; ks++)
                mmah(S[n1], Qa[ks][0], Qa[ks][1], Qa[ks][2], Qa[ks][3],
                     bk1[2 * ks], bk1[2 * ks + 1]);
        }

        float mx0 = fmaxf(S[0][0], S[0][1]);
        float mx1 = fmaxf(S[0][2], S[0][3]);
#pragma unroll
        for (int nt = 1; nt < 8; nt++) {
            mx0 = fmaxf(mx0, fmaxf(S[nt][0], S[nt][1]));
            mx1 = fmaxf(mx1, fmaxf(S[nt][2], S[nt][3]));
        }
        mx0 = fmaxf(mx0, __shfl_xor_sync(0xffffffffu, mx0, 1));
        mx0 = fmaxf(mx0, __shfl_xor_sync(0xffffffffu, mx0, 2));
        mx1 = fmaxf(mx1, __shfl_xor_sync(0xffffffffu, mx1, 1));
        mx1 = fmaxf(mx1, __shfl_xor_sync(0xffffffffu, mx1, 2));

        float mn0 = fmaxf(m0, mx0), mn1 = fmaxf(m1, mx1);
        float corr0 = ex2f((m0 - mn0) * C);
        float corr1 = ex2f((m1 - mn1) * C);
        m0 = mn0; m1 = mn1;
        float mc0 = mn0 * C, mc1 = mn1 * C;

        uint32_t P01[8], P23[8];
#pragma unroll
        for (int nt = 0; nt < 8; nt++) {
            P01[nt] = ex2h2(cvt2h(fmaf(S[nt][1], C, -mc0), fmaf(S[nt][0], C, -mc0)));
            P23[nt] = ex2h2(cvt2h(fmaf(S[nt][3], C, -mc1), fmaf(S[nt][2], C, -mc1)));
        }

        uint32_t s01 = hadd2u(hadd2u(hadd2u(P01[0], P01[1]), hadd2u(P01[2], P01[3])),
                              hadd2u(hadd2u(P01[4], P01[5]), hadd2u(P01[6], P01[7])));
        uint32_t s23 = hadd2u(hadd2u(hadd2u(P23[0], P23[1]), hadd2u(P23[2], P23[3])),
                              hadd2u(hadd2u(P23[4], P23[5]), hadd2u(P23[6], P23[7])));
        float rs0 = h2sumf(s01), rs1 = h2sumf(s23);
        rs0 += __shfl_xor_sync(0xffffffffu, rs0, 1);
        rs0 += __shfl_xor_sync(0xffffffffu, rs0, 2);
        rs1 += __shfl_xor_sync(0xffffffffu, rs1, 1);
        rs1 += __shfl_xor_sync(0xffffffffu, rs1, 2);
        l0 = l0 * corr0 + rs0;
        l1 = l1 * corr1 + rs1;

#pragma unroll
        for (int nt = 0; nt < 8; nt++) {
            O[nt][0] *= corr0; O[nt][1] *= corr0;
            O[nt][2] *= corr1; O[nt][3] *= corr1;
        }

        // O += P V — pairwise-hoisted V fragments
#pragma unroll
        for (int np = 0; np < 4; np++) {
            int n0 = 2 * np, n1 = 2 * np + 1;
            uint32_t bv0[8], bv1[8];
            uint32_t va0 = vbase + ((n0 * 8) << 1);
            uint32_t va1 = vbase + ((n1 * 8) << 1);
            ldm4t(bv0,     va0);
            ldm4t(bv0 + 4, va0 + ((32 * 72) << 1));
            ldm4t(bv1,     va1);
            ldm4t(bv1 + 4, va1 + ((32 * 72) << 1));
#pragma unroll
            for (int ks = 0; ks < 4; ks++)
                mmah(O[n0], P01[2 * ks], P23[2 * ks], P01[2 * ks + 1], P23[2 * ks + 1],
                     bv0[2 * ks], bv0[2 * ks + 1]);
#pragma unroll
            for (int ks = 0; ks < 4; ks++)
                mmah(O[n1], P01[2 * ks], P23[2 * ks], P01[2 * ks + 1], P23[2 * ks + 1],
                     bv1[2 * ks], bv1[2 * ks + 1]);
        }
    }

    float inv0 = 1.0f / l0, inv1 = 1.0f / l1;
    size_t cb = (size_t)bh * TKN * DK;
    int r0 = t0 + wq * 64 + wi * 16 + g;
#pragma unroll
    for (int nt = 0; nt < 8; nt++) {
        int col = nt * 8 + 2 * tg;
        *(__half2*)(g_ctxh + cb + (size_t)r0 * DK + col) =
            __floats2half2_rn(O[nt][0] * inv0, O[nt][1] * inv0);
        *(__half2*)(g_ctxh + cb + (size_t)(r0 + 8) * DK + col) =
            __floats2half2_rn(O[nt][2] * inv1, O[nt][3] * inv1);
    }
}

// ---------------------------------------------------------------------------
// Kernel 3: output projection (R14, frozen). 128x128, 4-stage ring,
// distance 2, hoisted fragment loads.
// ---------------------------------------------------------------------------
#define O_BH 5120
#define O_STAGE_B 20480

__global__ __launch_bounds__(256, 2) void outproj_kernel(
    const float* __restrict__ bo, float* __restrict__ out)
{
    extern __shared__ __half sdyn2[];
    __shared__ float sBias[128];

    int j0 = blockIdx.x * 128;
    int m0 = blockIdx.y * 128;

    int tid = threadIdx.x;
    int lane = tid & 31, w = tid >> 5;
    int wm = w & 3, wn = w >> 2;
    int g = lane >> 2, tg = lane & 3;

    if (tid < 128) sBias[tid] = bo[j0 + tid];

    uint32_t sb0 = cvta_s(sdyn2);
    int xrow = tid >> 2, xseg = tid & 3;

    float acc[2][8][4];
#pragma unroll
    for (int mt = 0; mt < 2; mt++)
#pragma unroll
        for (int nt = 0; nt < 8; nt++)
#pragma unroll
            for (int q = 0; q < 4; q++) acc[mt][nt][q] = 0.0f;

    int arow = wm * 32 + ((lane >> 3) & 1) * 8 + (lane & 7);
    int acol = (lane >> 4) * 8;
    uint32_t a_off = (uint32_t)(arow * 40 + acol) * 2;
    uint32_t k_off = (uint32_t)((lane & 7) * 40 + (lane >> 3) * 8) * 2;

    auto stage = [&](int s, int d0) {
        uint32_t base = sb0 + s * O_STAGE_B;
#pragma unroll
        for (int i = 0; i < 2; i++) {
            int r = xrow + i * 64;
            uint32_t dof = (uint32_t)(r * 40 + xseg * 8) * 2;
            cp16(base + dof,            g_ctxh + (size_t)(m0 + r) * DM + d0 + xseg * 8);
            cp16(base + O_BH * 2 + dof, g_Wof  + (size_t)(j0 + r) * DM + d0 + xseg * 8);
        }
        cpcommit();
    };

    stage(0, 0); stage(1, 32);

    const int nIter = DM / 32;
    for (int it = 0; it < nIter; it++) {
        if (it + 2 < nIter) { stage((it + 2) & 3, (it + 2) * 32); cpwait<2>(); }
        else if (it + 1 < nIter) cpwait<1>();
        else cpwait<0>();
        __syncthreads();

        uint32_t base = sb0 + (it & 3) * O_STAGE_B;
        uint32_t abh = base + a_off;
        uint32_t kbh = base + O_BH * 2 + k_off;

        uint32_t AH[2][2][4];
#pragma unroll
        for (int mt = 0; mt < 2; mt++)
#pragma unroll
            for (int ks = 0; ks < 2; ks++)
                ldm4(AH[mt][ks], abh + (mt * 16 * 40 + ks * 16) * 2);

        uint32_t BH[8][4];
#pragma unroll
        for (int nt = 0; nt < 8; nt++)
            ldm4(BH[nt], kbh + ((wn * 64 + nt * 8) * 40) * 2);

#pragma unroll
        for (int nt = 0; nt < 8; nt++)
#pragma unroll
            for (int ks = 0; ks < 2; ks++)
#pragma unroll
                for (int mt = 0; mt < 2; mt++)
                    mmah(acc[mt][nt],
                         AH[mt][ks][0], AH[mt][ks][1], AH[mt][ks][2], AH[mt][ks][3],
                         BH[nt][2 * ks], BH[nt][2 * ks + 1]);
    }

#pragma unroll
    for (int mt = 0; mt < 2; mt++) {
        int r0 = m0 + wm * 32 + mt * 16 + g;
#pragma unroll
        for (int nt = 0; nt < 8; nt++) {
            int cl = wn * 64 + nt * 8 + 2 * tg;
            float b0v = sBias[cl], b1v = sBias[cl + 1];
            *(float2*)(out + (size_t)r0 * DM + j0 + cl) =
                make_float2(acc[mt][nt][0] + b0v, acc[mt][nt][1] + b1v);
            *(float2*)(out + (size_t)(r0 + 8) * DM + j0 + cl) =
                make_float2(acc[mt][nt][2] + b0v, acc[mt][nt][3] + b1v);
        }
    }
}

// ---------------------------------------------------------------------------
extern "C" void kernel_launch(void* const* d_in, const int* in_sizes, int n_in,
                              void* d_out, int out_size)
{
    const float* Q  = (const float*)d_in[0];
    const float* K  = (const float*)d_in[1];
    const float* V  = (const float*)d_in[2];
    const float* Wq = (const float*)d_in[3];
    const float* bq = (const float*)d_in[4];
    const float* Wk = (const float*)d_in[5];
    const float* bk = (const float*)d_in[6];
    const float* Wv = (const float*)d_in[7];
    const float* bv = (const float*)d_in[8];
    const float* Wo = (const float*)d_in[9];
    const float* bo = (const float*)d_in[10];
    float* out = (float*)d_out;

    cudaFuncSetAttribute(proj_kernel, cudaFuncAttributeMaxDynamicSharedMemorySize, 4 * P_STAGE_B);
    cudaFuncSetAttribute(outproj_kernel, cudaFuncAttributeMaxDynamicSharedMemorySize, 4 * O_STAGE_B);

    dim3 gs(256, 7);
    split_kernel<<<gs, 256>>>(Q, K, V, Wq, Wk, Wv, Wo);

    dim3 g1(TKN / 128, B_SZ * 8, 3);
    proj_kernel<<<g1, 256, 4 * P_STAGE_B>>>(bq, bk, bv);

    dim3 g2(TKN / 128, B_SZ * HEADS);
    flash_kernel<<<g2, 256>>>();

    dim3 g3(DM / 128, (B_SZ * TKN) / 128);
    outproj_kernel<<<g3, 256, 4 * O_STAGE_B>>>(bo, out);
}

// round 16
// speedup vs baseline: 1.3165x; 1.0528x over previous
#include <cuda_runtime.h>
#include <cuda_fp16.h>
#include <cstdint>

#define B_SZ  2
#define HEADS 16
#define TKN   2048
#define DM    1024
#define DK    64

// ---- fp16 mma / ldmatrix / f16x2 helpers ----
__device__ __forceinline__ uint32_t cvta_s(const void* p) {
    return (uint32_t)__cvta_generic_to_shared(p);
}
__device__ __forceinline__ void ldm4(uint32_t* r, uint32_t a) {
    asm volatile("ldmatrix.sync.aligned.m8n8.x4.shared.b16 {%0,%1,%2,%3},[%4];"
        : "=r"(r[0]), "=r"(r[1]), "=r"(r[2]), "=r"(r[3]) : "r"(a));
}
__device__ __forceinline__ void ldm4t(uint32_t* r, uint32_t a) {
    asm volatile("ldmatrix.sync.aligned.m8n8.x4.trans.shared.b16 {%0,%1,%2,%3},[%4];"
        : "=r"(r[0]), "=r"(r[1]), "=r"(r[2]), "=r"(r[3]) : "r"(a));
}
__device__ __forceinline__ void mmah(float* d, uint32_t a0, uint32_t a1, uint32_t a2,
                                     uint32_t a3, uint32_t b0, uint32_t b1) {
    asm("mma.sync.aligned.m16n8k16.row.col.f32.f16.f16.f32 "
        "{%0,%1,%2,%3},{%4,%5,%6,%7},{%8,%9},{%0,%1,%2,%3};"
        : "+f"(d[0]), "+f"(d[1]), "+f"(d[2]), "+f"(d[3])
        : "r"(a0), "r"(a1), "r"(a2), "r"(a3), "r"(b0), "r"(b1));
}
__device__ __forceinline__ uint32_t cvt2h(float hi, float lo) {
    uint32_t d; asm("cvt.rn.f16x2.f32 %0, %1, %2;" : "=r"(d) : "f"(hi), "f"(lo)); return d;
}
__device__ __forceinline__ uint32_t ex2h2(uint32_t x) {
    uint32_t d; asm("ex2.approx.f16x2 %0, %1;" : "=r"(d) : "r"(x)); return d;
}
__device__ __forceinline__ float ex2f(float x) {
    float d; asm("ex2.approx.ftz.f32 %0, %1;" : "=f"(d) : "f"(x)); return d;
}
__device__ __forceinline__ uint32_t hadd2u(uint32_t a, uint32_t b) {
    uint32_t d; asm("add.rn.f16x2 %0, %1, %2;" : "=r"(d) : "r"(a), "r"(b)); return d;
}
__device__ __forceinline__ float h2sumf(uint32_t h) {
    __half2 v = *(__half2*)&h;
    return __low2float(v) + __high2float(v);
}
// cp.async 16B, L2-only (.cg)
__device__ __forceinline__ void cp16(uint32_t d, const void* s) {
    asm volatile("cp.async.cg.shared.global [%0], [%1], 16;" :: "r"(d), "l"(s));
}
__device__ __forceinline__ void cpcommit() { asm volatile("cp.async.commit_group;"); }
template <int N>
__device__ __forceinline__ void cpwait() {
    asm volatile("cp.async.wait_group %0;" :: "n"(N));
}

// ---- device-global scratch (no allocation) ----
__device__ __half g_Xf[3][B_SZ * TKN * DM];
__device__ __half g_Wf[3][HEADS * DM * DK];
__device__ __half g_Wof[DM * DM];
__device__ __half g_Qh[B_SZ * HEADS * TKN * DK]; // pre-scaled by 1/8
__device__ __half g_Kh[B_SZ * HEADS * TKN * DK];
__device__ __half g_Vh[B_SZ * HEADS * TKN * DK];
__device__ __half g_ctxh[B_SZ * HEADS * TKN * DK];

// ---------------------------------------------------------------------------
// Kernel 0: fused f32 -> f16 convert for all 7 tensors.
// ---------------------------------------------------------------------------
__global__ __launch_bounds__(256) void split_kernel(
    const float* __restrict__ Q, const float* __restrict__ K, const float* __restrict__ V,
    const float* __restrict__ Wq, const float* __restrict__ Wk, const float* __restrict__ Wv,
    const float* __restrict__ Wo)
{
    int y = blockIdx.y;
    const float* src; __half* dst; int n4;
    switch (y) {
        case 0: src = Q;  dst = g_Xf[0]; n4 = (B_SZ * TKN * DM) / 4; break;
        case 1: src = K;  dst = g_Xf[1]; n4 = (B_SZ * TKN * DM) / 4; break;
        case 2: src = V;  dst = g_Xf[2]; n4 = (B_SZ * TKN * DM) / 4; break;
        case 3: src = Wq; dst = g_Wf[0]; n4 = (HEADS * DM * DK) / 4; break;
        case 4: src = Wk; dst = g_Wf[1]; n4 = (HEADS * DM * DK) / 4; break;
        case 5: src = Wv; dst = g_Wf[2]; n4 = (HEADS * DM * DK) / 4; break;
        default: src = Wo; dst = g_Wof;  n4 = (DM * DM) / 4; break;
    }
    int tid0 = blockIdx.x * blockDim.x + threadIdx.x;
    int stride = gridDim.x * blockDim.x;
    for (int i = tid0 * 2; i < n4; i += stride * 2) {
        float4 v0 = ((const float4*)src)[i];
        ((__half2*)dst)[2 * i]     = __floats2half2_rn(v0.x, v0.y);
        ((__half2*)dst)[2 * i + 1] = __floats2half2_rn(v0.z, v0.w);
        if (i + 1 < n4) {
            float4 v1 = ((const float4*)src)[i + 1];
            ((__half2*)dst)[2 * i + 2] = __floats2half2_rn(v1.x, v1.y);
            ((__half2*)dst)[2 * i + 3] = __floats2half2_rn(v1.z, v1.w);
        }
    }
}

// ---------------------------------------------------------------------------
// Kernel 1: QKV projections (frozen at R14/R15 best).
// ---------------------------------------------------------------------------
#define P_W   5120
#define P_STAGE_B 18944

__global__ __launch_bounds__(256, 2) void proj_kernel(
    const float* __restrict__ bq, const float* __restrict__ bk, const float* __restrict__ bv)
{
    extern __shared__ __half sdyn[];
    __shared__ float sBias[128];

    int z = blockIdx.z;
    const float* bias = (z == 0) ? bq : (z == 1) ? bk : bv;
    __half* out = (z == 0) ? g_Qh : (z == 1) ? g_Kh : g_Vh;
    float oscale = (z == 0) ? 0.125f : 1.0f;

    int y = blockIdx.y;
    int b = y >> 3, h0 = (y & 7) * 2;
    int t0 = blockIdx.x * 128;

    const __half* Xp = g_Xf[z] + ((size_t)b * TKN + t0) * DM;
    const __half* Wp = g_Wf[z] + (size_t)h0 * DM * DK;

    int tid = threadIdx.x;
    int lane = tid & 31, w = tid >> 5;
    int wm = w & 3, wn = w >> 2;
    int g = lane >> 2, tg = lane & 3;

    if (tid < 128) sBias[tid] = bias[h0 * DK + tid];

    uint32_t sb0 = cvta_s(sdyn);

    int xrow = tid >> 2, xseg = tid & 3;
    int wrow_c = tid >> 4, wcol_c = (tid & 15) * 8;
    size_t wso = (size_t)(wcol_c >= 64 ? DM * DK : 0) + (size_t)wrow_c * DK + (wcol_c & 63);

    float acc[2][8][4];
#pragma unroll
    for (int mt = 0; mt < 2; mt++)
#pragma unroll
        for (int nt = 0; nt < 8; nt++)
#pragma unroll
            for (int q = 0; q < 4; q++) acc[mt][nt][q] = 0.0f;

    int arow = wm * 32 + ((lane >> 3) & 1) * 8 + (lane & 7);
    int acol = (lane >> 4) * 8;
    uint32_t a_off = (uint32_t)(arow * 40 + acol) * 2;
    uint32_t w_off = ((uint32_t)((lane >> 3) * 8 + (lane & 7)) * 136) * 2;

    auto stage = [&](int s, int d0) {
        uint32_t base = sb0 + s * P_STAGE_B;
#pragma unroll
        for (int i = 0; i < 2; i++) {
            int r = xrow + i * 64;
            cp16(base + (uint32_t)(r * 40 + xseg * 8) * 2,
                 Xp + (size_t)r * DM + d0 + xseg * 8);
        }
#pragma unroll
        for (int i = 0; i < 2; i++) {
            int r = wrow_c + i * 16;
            cp16(base + P_W * 2 + (uint32_t)(r * 136 + wcol_c) * 2,
                 Wp + wso + (size_t)(d0 + i * 16) * DK);
        }
        cpcommit();
    };

    stage(0, 0); stage(1, 32);

    const int nIter = DM / 32;
    for (int it = 0; it < nIter; it++) {
        if (it + 2 < nIter) { stage((it + 2) & 3, (it + 2) * 32); cpwait<2>(); }
        else if (it + 1 < nIter) cpwait<1>();
        else cpwait<0>();
        __syncthreads();

        uint32_t base = sb0 + (it & 3) * P_STAGE_B;
        uint32_t abh = base + a_off;
        uint32_t wbh = base + P_W * 2 + w_off;

        uint32_t AH[2][2][4];
#pragma unroll
        for (int mt = 0; mt < 2; mt++)
#pragma unroll
            for (int ks = 0; ks < 2; ks++)
                ldm4(AH[mt][ks], abh + (mt * 16 * 40 + ks * 16) * 2);

        uint32_t BH[8][4];
#pragma unroll
        for (int nt = 0; nt < 8; nt++)
            ldm4t(BH[nt], wbh + (wn * 64 + nt * 8) * 2);

#pragma unroll
        for (int nt = 0; nt < 8; nt++)
#pragma unroll
            for (int ks = 0; ks < 2; ks++)
#pragma unroll
                for (int mt = 0; mt < 2; mt++)
                    mmah(acc[mt][nt],
                         AH[mt][ks][0], AH[mt][ks][1], AH[mt][ks][2], AH[mt][ks][3],
                         BH[nt][2 * ks], BH[nt][2 * ks + 1]);
    }

    __half* outh = out + ((size_t)(b * HEADS + h0 + wn) * TKN + t0) * DK;
#pragma unroll
    for (int mt = 0; mt < 2; mt++) {
        int r0 = wm * 32 + mt * 16 + g;
#pragma unroll
        for (int nt = 0; nt < 8; nt++) {
            int cl = nt * 8 + 2 * tg;
            float b0v = sBias[wn * 64 + cl], b1v = sBias[wn * 64 + cl + 1];
            *(__half2*)(outh + (size_t)r0 * DK + cl) =
                __floats2half2_rn((acc[mt][nt][0] + b0v) * oscale, (acc[mt][nt][1] + b1v) * oscale);
            *(__half2*)(outh + (size_t)(r0 + 8) * DK + cl) =
                __floats2half2_rn((acc[mt][nt][2] + b0v) * oscale, (acc[mt][nt][3] + b1v) * oscale);
        }
    }
}

// ---------------------------------------------------------------------------
// Kernel 2: flash attention. 128 queries / 8 warps per CTA.
// NEW: 4-slot K/V ring in dynamic smem, prefetch distance 2 -> ONE sync/chunk
// (exact proj/outproj-proven ring discipline, power-of-2 slot indexing).
// Layout (bytes): Q[128][72] @0 (18432); slot s @ 18432 + s*18432
// (K @+0 9216, V @+9216). Total 92160 B dynamic; 2 CTAs/SM.
// ---------------------------------------------------------------------------
#define F_SLOT_B 18432
#define F_DYN_B  (5 * 18432)

__global__ __launch_bounds__(256) void flash_kernel()
{
    extern __shared__ __half fsm[];

    const float C = 1.4426950408889634f;

    int bh = blockIdx.y;
    int t0 = blockIdx.x * 128;
    const __half* Qp = g_Qh + (size_t)bh * TKN * DK;
    const __half* Kp = g_Kh + (size_t)bh * TKN * DK;
    const __half* Vp = g_Vh + (size_t)bh * TKN * DK;

    int tid = threadIdx.x;
    int lane = tid & 31, w = tid >> 5;
    int wq = w >> 2, wi = w & 3;
    int g = lane >> 2, tg = lane & 3;

    uint32_t sm0 = cvta_s(fsm);
    uint32_t kv0 = sm0 + F_SLOT_B;        // slot 0 base

    auto stagekv = [&](int slot, int s0) {
        uint32_t base = kv0 + slot * F_SLOT_B;
#pragma unroll
        for (int i = 0; i < 2; i++) {
            int idx = i * 256 + tid;
            int r = idx >> 3, c = idx & 7;
            uint32_t dof = (uint32_t)(r * 72 + c * 8) * 2;
            cp16(base + dof,        Kp + (size_t)(s0 + r) * DK + c * 8);
            cp16(base + 9216 + dof, Vp + (size_t)(s0 + r) * DK + c * 8);
        }
        cpcommit();
    };

    stagekv(0, 0); stagekv(1, 64);

    // stage Q (plain stores into dynamic smem)
#pragma unroll
    for (int i = 0; i < 4; i++) {
        int idx = i * 256 + tid;
        int r = idx >> 3, c = idx & 7;
        *(uint4*)&fsm[r * 72 + c * 8] = *(const uint4*)(Qp + (size_t)(t0 + r) * DK + c * 8);
    }
    __syncthreads();

    uint32_t Qa[4][4];
    {
        int qrow = wq * 64 + wi * 16 + ((lane >> 3) & 1) * 8 + (lane & 7);
        int qcol = (lane >> 4) * 8;
        uint32_t qbase = sm0 + (uint32_t)(qrow * 72 + qcol) * 2;
#pragma unroll
        for (int ks = 0; ks < 4; ks++) ldm4(Qa[ks], qbase + ks * 32);
    }

    uint32_t k_off = (((lane & 7) * 72 + (lane >> 3) * 8) << 1);
    uint32_t v_off = 9216 + ((((lane >> 3) * 8 + (lane & 7)) * 72) << 1);

    float m0 = -1e30f, m1 = -1e30f, l0 = 0.0f, l1 = 0.0f;
    float O[8][4];
#pragma unroll
    for (int nt = 0; nt < 8; nt++)
#pragma unroll
        for (int q = 0; q < 4; q++) O[nt][q] = 0.0f;

    const int nCh = TKN / 64;
    for (int it = 0; it < nCh; it++) {
        // distance-2 prefetch into 4-slot ring: (it+2)&3 never collides with
        // the slot slow readers may still hold ((it-1)&3) -> single sync/chunk.
        if (it + 2 < nCh) { stagekv((it + 2) & 3, (it + 2) * 64); cpwait<2>(); }
        else if (it + 1 < nCh) cpwait<1>();
        else cpwait<0>();
        __syncthreads();

        uint32_t slot = kv0 + (it & 3) * F_SLOT_B;
        uint32_t kbase = slot + k_off;
        uint32_t vbase = slot + v_off;

        // S = Q K^T — pairwise-hoisted K fragments
        float S[8][4];
#pragma unroll
        for (int nt = 0; nt < 8; nt++)
#pragma unroll
            for (int q = 0; q < 4; q++) S[nt][q] = 0.0f;
#pragma unroll
        for (int np = 0; np < 4; np++) {
            int n0 = 2 * np, n1 = 2 * np + 1;
            uint32_t bk0[8], bk1[8];
            uint32_t ka0 = kbase + ((n0 * 8 * 72) << 1);
            uint32_t ka1 = kbase + ((n1 * 8 * 72) << 1);
            ldm4(bk0,     ka0);
            ldm4(bk0 + 4, ka0 + 64);
            ldm4(bk1,     ka1);
            ldm4(bk1 + 4, ka1 + 64);
#pragma unroll
            for (int ks = 0; ks < 4; ks++)
                mmah(S[n0], Qa[ks][0], Qa[ks][1], Qa[ks][2], Qa[ks][3],
                     bk0[2 * ks], bk0[2 * ks + 1]);
#pragma unroll
            for (int ks = 0; ks < 4; ks++)
                mmah(S[n1], Qa[ks][0], Qa[ks][1], Qa[ks][2], Qa[ks][3],
                     bk1[2 * ks], bk1[2 * ks + 1]);
        }

        float mx0 = fmaxf(S[0][0], S[0][1]);
        float mx1 = fmaxf(S[0][2], S[0][3]);
#pragma unroll
        for (int nt = 1; nt < 8; nt++) {
            mx0 = fmaxf(mx0, fmaxf(S[nt][0], S[nt][1]));
            mx1 = fmaxf(mx1, fmaxf(S[nt][2], S[nt][3]));
        }
        mx0 = fmaxf(mx0, __shfl_xor_sync(0xffffffffu, mx0, 1));
        mx0 = fmaxf(mx0, __shfl_xor_sync(0xffffffffu, mx0, 2));
        mx1 = fmaxf(mx1, __shfl_xor_sync(0xffffffffu, mx1, 1));
        mx1 = fmaxf(mx1, __shfl_xor_sync(0xffffffffu, mx1, 2));

        float mn0 = fmaxf(m0, mx0), mn1 = fmaxf(m1, mx1);
        float corr0 = ex2f((m0 - mn0) * C);
        float corr1 = ex2f((m1 - mn1) * C);
        m0 = mn0; m1 = mn1;
        float mc0 = mn0 * C, mc1 = mn1 * C;

        uint32_t P01[8], P23[8];
#pragma unroll
        for (int nt = 0; nt < 8; nt++) {
            P01[nt] = ex2h2(cvt2h(fmaf(S[nt][1], C, -mc0), fmaf(S[nt][0], C, -mc0)));
            P23[nt] = ex2h2(cvt2h(fmaf(S[nt][3], C, -mc1), fmaf(S[nt][2], C, -mc1)));
        }

        uint32_t s01 = hadd2u(hadd2u(hadd2u(P01[0], P01[1]), hadd2u(P01[2], P01[3])),
                              hadd2u(hadd2u(P01[4], P01[5]), hadd2u(P01[6], P01[7])));
        uint32_t s23 = hadd2u(hadd2u(hadd2u(P23[0], P23[1]), hadd2u(P23[2], P23[3])),
                              hadd2u(hadd2u(P23[4], P23[5]), hadd2u(P23[6], P23[7])));
        float rs0 = h2sumf(s01), rs1 = h2sumf(s23);
        rs0 += __shfl_xor_sync(0xffffffffu, rs0, 1);
        rs0 += __shfl_xor_sync(0xffffffffu, rs0, 2);
        rs1 += __shfl_xor_sync(0xffffffffu, rs1, 1);
        rs1 += __shfl_xor_sync(0xffffffffu, rs1, 2);
        l0 = l0 * corr0 + rs0;
        l1 = l1 * corr1 + rs1;

#pragma unroll
        for (int nt = 0; nt < 8; nt++) {
            O[nt][0] *= corr0; O[nt][1] *= corr0;
            O[nt][2] *= corr1; O[nt][3] *= corr1;
        }

        // O += P V — pairwise-hoisted V fragments
#pragma unroll
        for (int np = 0; np < 4; np++) {
            int n0 = 2 * np, n1 = 2 * np + 1;
            uint32_t bv0[8], bv1[8];
            uint32_t va0 = vbase + ((n0 * 8) << 1);
            uint32_t va1 = vbase + ((n1 * 8) << 1);
            ldm4t(bv0,     va0);
            ldm4t(bv0 + 4, va0 + ((32 * 72) << 1));
            ldm4t(bv1,     va1);
            ldm4t(bv1 + 4, va1 + ((32 * 72) << 1));
#pragma unroll
            for (int ks = 0; ks < 4; ks++)
                mmah(O[n0], P01[2 * ks], P23[2 * ks], P01[2 * ks + 1], P23[2 * ks + 1],
                     bv0[2 * ks], bv0[2 * ks + 1]);
#pragma unroll
            for (int ks = 0; ks < 4; ks++)
                mmah(O[n1], P01[2 * ks], P23[2 * ks], P01[2 * ks + 1], P23[2 * ks + 1],
                     bv1[2 * ks], bv1[2 * ks + 1]);
        }
    }

    float inv0 = 1.0f / l0, inv1 = 1.0f / l1;
    size_t cb = (size_t)bh * TKN * DK;
    int r0 = t0 + wq * 64 + wi * 16 + g;
#pragma unroll
    for (int nt = 0; nt < 8; nt++) {
        int col = nt * 8 + 2 * tg;
        *(__half2*)(g_ctxh + cb + (size_t)r0 * DK + col) =
            __floats2half2_rn(O[nt][0] * inv0, O[nt][1] * inv0);
        *(__half2*)(g_ctxh + cb + (size_t)(r0 + 8) * DK + col) =
            __floats2half2_rn(O[nt][2] * inv1, O[nt][3] * inv1);
    }
}

// ---------------------------------------------------------------------------
// Kernel 3: output projection (frozen at R14/R15 best).
// ---------------------------------------------------------------------------
#define O_BH 5120
#define O_STAGE_B 20480

__global__ __launch_bounds__(256, 2) void outproj_kernel(
    const float* __restrict__ bo, float* __restrict__ out)
{
    extern __shared__ __half sdyn2[];
    __shared__ float sBias[128];

    int j0 = blockIdx.x * 128;
    int m0 = blockIdx.y * 128;

    int tid = threadIdx.x;
    int lane = tid & 31, w = tid >> 5;
    int wm = w & 3, wn = w >> 2;
    int g = lane >> 2, tg = lane & 3;

    if (tid < 128) sBias[tid] = bo[j0 + tid];

    uint32_t sb0 = cvta_s(sdyn2);
    int xrow = tid >> 2, xseg = tid & 3;

    float acc[2][8][4];
#pragma unroll
    for (int mt = 0; mt < 2; mt++)
#pragma unroll
        for (int nt = 0; nt < 8; nt++)
#pragma unroll
            for (int q = 0; q < 4; q++) acc[mt][nt][q] = 0.0f;

    int arow = wm * 32 + ((lane >> 3) & 1) * 8 + (lane & 7);
    int acol = (lane >> 4) * 8;
    uint32_t a_off = (uint32_t)(arow * 40 + acol) * 2;
    uint32_t k_off = (uint32_t)((lane & 7) * 40 + (lane >> 3) * 8) * 2;

    auto stage = [&](int s, int d0) {
        uint32_t base = sb0 + s * O_STAGE_B;
#pragma unroll
        for (int i = 0; i < 2; i++) {
            int r = xrow + i * 64;
            uint32_t dof = (uint32_t)(r * 40 + xseg * 8) * 2;
            cp16(base + dof,            g_ctxh + (size_t)(m0 + r) * DM + d0 + xseg * 8);
            cp16(base + O_BH * 2 + dof, g_Wof  + (size_t)(j0 + r) * DM + d0 + xseg * 8);
        }
        cpcommit();
    };

    stage(0, 0); stage(1, 32);

    const int nIter = DM / 32;
    for (int it = 0; it < nIter; it++) {
        if (it + 2 < nIter) { stage((it + 2) & 3, (it + 2) * 32); cpwait<2>(); }
        else if (it + 1 < nIter) cpwait<1>();
        else cpwait<0>();
        __syncthreads();

        uint32_t base = sb0 + (it & 3) * O_STAGE_B;
        uint32_t abh = base + a_off;
        uint32_t kbh = base + O_BH * 2 + k_off;

        uint32_t AH[2][2][4];
#pragma unroll
        for (int mt = 0; mt < 2; mt++)
#pragma unroll
            for (int ks = 0; ks < 2; ks++)
                ldm4(AH[mt][ks], abh + (mt * 16 * 40 + ks * 16) * 2);

        uint32_t BH[8][4];
#pragma unroll
        for (int nt = 0; nt < 8; nt++)
            ldm4(BH[nt], kbh + ((wn * 64 + nt * 8) * 40) * 2);

#pragma unroll
        for (int nt = 0; nt < 8; nt++)
#pragma unroll
            for (int ks = 0; ks < 2; ks++)
#pragma unroll
                for (int mt = 0; mt < 2; mt++)
                    mmah(acc[mt][nt],
                         AH[mt][ks][0], AH[mt][ks][1], AH[mt][ks][2], AH[mt][ks][3],
                         BH[nt][2 * ks], BH[nt][2 * ks + 1]);
    }

#pragma unroll
    for (int mt = 0; mt < 2; mt++) {
        int r0 = m0 + wm * 32 + mt * 16 + g;
#pragma unroll
        for (int nt = 0; nt < 8; nt++) {
            int cl = wn * 64 + nt * 8 + 2 * tg;
            float b0v = sBias[cl], b1v = sBias[cl + 1];
            *(float2*)(out + (size_t)r0 * DM + j0 + cl) =
                make_float2(acc[mt][nt][0] + b0v, acc[mt][nt][1] + b1v);
            *(float2*)(out + (size_t)(r0 + 8) * DM + j0 + cl) =
                make_float2(acc[mt][nt][2] + b0v, acc[mt][nt][3] + b1v);
        }
    }
}

// ---------------------------------------------------------------------------
extern "C" void kernel_launch(void* const* d_in, const int* in_sizes, int n_in,
                              void* d_out, int out_size)
{
    const float* Q  = (const float*)d_in[0];
    const float* K  = (const float*)d_in[1];
    const float* V  = (const float*)d_in[2];
    const float* Wq = (const float*)d_in[3];
    const float* bq = (const float*)d_in[4];
    const float* Wk = (const float*)d_in[5];
    const float* bk = (const float*)d_in[6];
    const float* Wv = (const float*)d_in[7];
    const float* bv = (const float*)d_in[8];
    const float* Wo = (const float*)d_in[9];
    const float* bo = (const float*)d_in[10];
    float* out = (float*)d_out;

    cudaFuncSetAttribute(proj_kernel, cudaFuncAttributeMaxDynamicSharedMemorySize, 4 * P_STAGE_B);
    cudaFuncSetAttribute(flash_kernel, cudaFuncAttributeMaxDynamicSharedMemorySize, F_DYN_B);
    cudaFuncSetAttribute(outproj_kernel, cudaFuncAttributeMaxDynamicSharedMemorySize, 4 * O_STAGE_B);

    dim3 gs(256, 7);
    split_kernel<<<gs, 256>>>(Q, K, V, Wq, Wk, Wv, Wo);

    dim3 g1(TKN / 128, B_SZ * 8, 3);
    proj_kernel<<<g1, 256, 4 * P_STAGE_B>>>(bq, bk, bv);

    dim3 g2(TKN / 128, B_SZ * HEADS);
    flash_kernel<<<g2, 256, F_DYN_B>>>();

    dim3 g3(DM / 128, (B_SZ * TKN) / 128);
    outproj_kernel<<<g3, 256, 4 * O_STAGE_B>>>(bo, out);
}